// round 12
// baseline (speedup 1.0000x reference)
#include <cuda_runtime.h>
#include <cuda_fp16.h>
#include <cstdint>
#include <math.h>

#define N_NODES 50000
#define N_PAD   50048          // padded to multiple of 128 for GEMM tiles
#define E_RAW   800000
#define ET      (E_RAW + N_NODES)
#define IN_F    256
#define HC      256            // HEADS * OUT_F
#define C_OUT   64
#define NEG_SLOPE 0.2f
#define NB_SCAN 49             // ceil(50000/1024)

// ---- scratch (static __device__ arrays; no runtime allocation) ----
__device__ __align__(16) __half g_xlh[N_NODES * HC];   // xl in fp16 (attn gathers this)
__device__ float g_xr[N_NODES * HC];
__device__ float g_out[N_NODES * C_OUT];
__device__ int   g_counts[N_NODES];
__device__ int   g_cursor[N_NODES];
__device__ int   g_offsets[N_NODES + 1];
__device__ int   g_src_sorted[ET];
__device__ int   g_bsum[64];
__device__ int   g_boff[64];
__device__ float g_sum[C_OUT];
__device__ float g_sumsq[C_OUT];
__device__ float g_scale[C_OUT];
__device__ float g_shift[C_OUT];
// fp16 operands: X rounded to fp16; W split hi/lo fp16 (2-term correction)
__device__ __align__(16) __half g_Xh[N_PAD * IN_F];
__device__ __align__(16) __half g_Bh[512 * IN_F];   // [n][k]; n<256: Wl col, else Wr
__device__ __align__(16) __half g_Bl[512 * IN_F];

// ---------------- helpers ----------------
__device__ __forceinline__ uint32_t smem_u32(const void* p) {
    uint32_t a;
    asm("{ .reg .u64 t; cvta.to.shared.u64 t, %1; cvt.u32.u64 %0, t; }" : "=r"(a) : "l"(p));
    return a;
}
__device__ __forceinline__ void cp16(uint32_t s, const void* g) {
    asm volatile("cp.async.cg.shared.global [%0], [%1], 16;" :: "r"(s), "l"(g));
}
#define CP_COMMIT() asm volatile("cp.async.commit_group;" ::: "memory")
#define CP_WAIT1()  asm volatile("cp.async.wait_group 1;" ::: "memory")
#define CP_WAIT0()  asm volatile("cp.async.wait_group 0;" ::: "memory")

__device__ __forceinline__ void mma_fp16(float* d, const uint32_t* a, const uint32_t* b) {
    asm volatile(
        "mma.sync.aligned.m16n8k16.row.col.f32.f16.f16.f32 "
        "{%0,%1,%2,%3}, {%4,%5,%6,%7}, {%8,%9}, {%0,%1,%2,%3};"
        : "+f"(d[0]), "+f"(d[1]), "+f"(d[2]), "+f"(d[3])
        : "r"(a[0]), "r"(a[1]), "r"(a[2]), "r"(a[3]), "r"(b[0]), "r"(b[1]));
}
__device__ __forceinline__ void ldsm4(uint32_t* r, uint32_t addr) {
    asm volatile("ldmatrix.sync.aligned.m8n8.x4.shared.b16 {%0,%1,%2,%3}, [%4];"
                 : "=r"(r[0]), "=r"(r[1]), "=r"(r[2]), "=r"(r[3]) : "r"(addr));
}

// ---------------- fp16 conversion (fused with pad) ----------------
__global__ void convx_kernel(const float* __restrict__ X) {
    int i = blockIdx.x * blockDim.x + threadIdx.x;
    const int real = N_NODES * IN_F / 4;
    const int total = N_PAD * IN_F / 4;
    if (i >= total) return;
    __half h[4];
    if (i < real) {
        float4 v = ((const float4*)X)[i];
        h[0] = __float2half_rn(v.x); h[1] = __float2half_rn(v.y);
        h[2] = __float2half_rn(v.z); h[3] = __float2half_rn(v.w);
    } else {
        h[0] = h[1] = h[2] = h[3] = __float2half_rn(0.f);
    }
    ((uint2*)g_Xh)[i] = *(uint2*)h;
}

// convb + zero scratch fused
__global__ void convb_kernel(const float* __restrict__ Wl, const float* __restrict__ Wr) {
    int i = blockIdx.x * blockDim.x + threadIdx.x;   // over 512*256 = 131072
    if (i < N_NODES) { g_counts[i] = 0; g_cursor[i] = 0; }
    if (i < C_OUT)   { g_sum[i] = 0.f; g_sumsq[i] = 0.f; }
    if (i >= 512 * IN_F) return;
    int n = i >> 8, k = i & 255;
    const float* W = (n < 256) ? Wl : Wr;
    float v = W[k * 256 + (n & 255)];
    __half h = __float2half_rn(v);
    __half l = __float2half_rn(v - __half2float(h));
    g_Bh[n * IN_F + k] = h;
    g_Bl[n * IN_F + k] = l;
}

// ---------------- mma.sync GEMM: Y[50000,512] = X @ [Wl|Wr] ----------------
// grid(4, 391). fp16 2-term split (Xh*Wh + Xh*Wl), fp32 accum, cp.async depth-2,
// ldmatrix fragment loads. bx<2 -> xl (fp16 out); bx>=2 -> xr (fp32 out).
#define LDB   40               // padded k-stride (halfs) -> conflict-free LDS/LDSM
#define TSZ   (128 * LDB)      // one operand tile, elems (5120)
#define BUFSZ (3 * TSZ)        // Ah | Bh | Bl
#define GSMEM (2 * BUFSZ * 2)  // bytes: 61440

__global__ void __launch_bounds__(256) gemm_mma_kernel() {
    extern __shared__ __align__(16) char dsm[];
    uint32_t sb = smem_u32(dsm);

    const int tid = threadIdx.x;
    const int wid = tid >> 5, lane = tid & 31;
    const int wm = wid & 3, wn = wid >> 2;          // 4 warps on M, 2 on N
    const int q = lane >> 2, c2 = (lane & 3) * 2;
    const int bx = blockIdx.x, by = blockIdx.y;
    const int rowG = by * 128;

    // per-lane ldmatrix byte offsets (relative to buffer base)
    const int la = lane & 15, ka = lane >> 4;                 // A tile lanes
    const int lbrow = (lane & 7) + ((lane >> 4) << 3);        // B tile lanes
    const int kb = (lane >> 3) & 1;
    uint32_t offA[2], offBh[4], offBl[4];
#pragma unroll
    for (int mt = 0; mt < 2; mt++)
        offA[mt] = ((wm * 32 + mt * 16 + la) * LDB + ka * 8) * 2;
#pragma unroll
    for (int p = 0; p < 4; p++) {
        uint32_t o = ((wn * 64 + p * 16 + lbrow) * LDB + kb * 8) * 2;
        offBh[p] = TSZ * 2 + o;
        offBl[p] = 2 * TSZ * 2 + o;
    }

    float acc[2][8][4];
#pragma unroll
    for (int mt = 0; mt < 2; mt++)
#pragma unroll
        for (int nt = 0; nt < 8; nt++)
#pragma unroll
            for (int j = 0; j < 4; j++) acc[mt][nt][j] = 0.f;

    auto prefetch = [&](int c, int b) {
        const int k0 = c * 32;
        const uint32_t base = sb + b * (BUFSZ * 2);
#pragma unroll
        for (int i = 0; i < 2; i++) {
            int idx = tid + i * 256;
            int r = idx >> 2, seg = idx & 3;
            uint32_t off = (r * LDB + seg * 8) * 2;
            long ga = (long)(rowG + r) * IN_F + k0 + seg * 8;
            long gb = (long)(bx * 128 + r) * IN_F + k0 + seg * 8;
            cp16(base + off,               g_Xh + ga);
            cp16(base + TSZ * 2 + off,     g_Bh + gb);
            cp16(base + 2 * TSZ * 2 + off, g_Bl + gb);
        }
        CP_COMMIT();
    };

    prefetch(0, 0);
    for (int c = 0; c < 8; c++) {
        if (c < 7) { prefetch(c + 1, (c + 1) & 1); CP_WAIT1(); }
        else       { CP_WAIT0(); }
        __syncthreads();

        const uint32_t bufbase = sb + (c & 1) * (BUFSZ * 2);

#pragma unroll
        for (int ks = 0; ks < 2; ks++) {
            const uint32_t kof = ks * 32;   // 16 halfs = 32 bytes
            uint32_t ah[2][4];
            ldsm4(ah[0], bufbase + offA[0] + kof);
            ldsm4(ah[1], bufbase + offA[1] + kof);
            uint32_t bh[8][2], bl[8][2];
#pragma unroll
            for (int p = 0; p < 4; p++) {
                uint32_t r4[4];
                ldsm4(r4, bufbase + offBh[p] + kof);
                bh[2 * p][0] = r4[0]; bh[2 * p][1] = r4[1];
                bh[2 * p + 1][0] = r4[2]; bh[2 * p + 1][1] = r4[3];
                ldsm4(r4, bufbase + offBl[p] + kof);
                bl[2 * p][0] = r4[0]; bl[2 * p][1] = r4[1];
                bl[2 * p + 1][0] = r4[2]; bl[2 * p + 1][1] = r4[3];
            }
#pragma unroll
            for (int mt = 0; mt < 2; mt++)
#pragma unroll
                for (int nt = 0; nt < 8; nt++) {
                    mma_fp16(acc[mt][nt], ah[mt], bh[nt]);
                    mma_fp16(acc[mt][nt], ah[mt], bl[nt]);
                }
        }
        __syncthreads();
    }

    const int colBase = (bx & 1) * 128;
    if (bx < 2) {   // xl -> fp16
#pragma unroll
        for (int mt = 0; mt < 2; mt++) {
            int r0 = rowG + wm * 32 + mt * 16 + q;
#pragma unroll
            for (int nt = 0; nt < 8; nt++) {
                int col = colBase + wn * 64 + nt * 8 + c2;
                if (r0 < N_NODES)
                    *(__half2*)(g_xlh + (long)r0 * HC + col) =
                        __floats2half2_rn(acc[mt][nt][0], acc[mt][nt][1]);
                if (r0 + 8 < N_NODES)
                    *(__half2*)(g_xlh + (long)(r0 + 8) * HC + col) =
                        __floats2half2_rn(acc[mt][nt][2], acc[mt][nt][3]);
            }
        }
    } else {        // xr -> fp32
#pragma unroll
        for (int mt = 0; mt < 2; mt++) {
            int r0 = rowG + wm * 32 + mt * 16 + q;
#pragma unroll
            for (int nt = 0; nt < 8; nt++) {
                int col = colBase + wn * 64 + nt * 8 + c2;
                if (r0 < N_NODES)
                    *(float2*)(g_xr + (long)r0 * HC + col) = make_float2(acc[mt][nt][0], acc[mt][nt][1]);
                if (r0 + 8 < N_NODES)
                    *(float2*)(g_xr + (long)(r0 + 8) * HC + col) = make_float2(acc[mt][nt][2], acc[mt][nt][3]);
            }
        }
    }
}

// ---------------- CSR build (dst-sorted) ----------------
__global__ void hist_kernel(const int* __restrict__ E) {
    int i = blockIdx.x * blockDim.x + threadIdx.x;
    if (i >= ET) return;
    int d = (i < E_RAW) ? E[E_RAW + i] : (i - E_RAW);
    atomicAdd(&g_counts[d], 1);
}

__global__ void scan1_kernel() {
    __shared__ int sh[1024];
    int b = blockIdx.x, t = threadIdx.x;
    int i = b * 1024 + t;
    int v = (i < N_NODES) ? g_counts[i] : 0;
    sh[t] = v;
    __syncthreads();
    for (int off = 1; off < 1024; off <<= 1) {
        int add = (t >= off) ? sh[t - off] : 0;
        __syncthreads();
        sh[t] += add;
        __syncthreads();
    }
    if (i < N_NODES) g_offsets[i + 1] = sh[t];
    if (t == 1023) g_bsum[b] = sh[1023];
}

__global__ void scan2_kernel() {
    __shared__ int sh[64];
    int t = threadIdx.x;
    int v = (t < NB_SCAN) ? g_bsum[t] : 0;
    sh[t] = v;
    __syncthreads();
    for (int off = 1; off < 64; off <<= 1) {
        int add = (t >= off) ? sh[t - off] : 0;
        __syncthreads();
        sh[t] += add;
        __syncthreads();
    }
    if (t < NB_SCAN) g_boff[t] = sh[t] - v;
}

__global__ void scan3_kernel() {
    int b = blockIdx.x;
    int i = b * 1024 + threadIdx.x;
    if (i < N_NODES) g_offsets[i + 1] += g_boff[b];
    if (i == 0) g_offsets[0] = 0;
}

__global__ void scatter_kernel(const int* __restrict__ E) {
    int i = blockIdx.x * blockDim.x + threadIdx.x;
    if (i >= ET) return;
    int s, d;
    if (i < E_RAW) { s = E[i]; d = E[E_RAW + i]; }
    else           { s = d = i - E_RAW; }
    int pos = atomicAdd(&g_cursor[d], 1);
    g_src_sorted[g_offsets[d] + pos] = s;
}

// ---------------- attention: one warp per destination node ----------------
// xl gathered as fp16 (one uint4 = the lane's 8 channels). 8-edge pipeline.
__device__ __forceinline__ void unpack8(const uint4& u, float* f) {
    float2 a = __half22float2(*(const __half2*)&u.x);
    float2 b = __half22float2(*(const __half2*)&u.y);
    float2 c = __half22float2(*(const __half2*)&u.z);
    float2 d = __half22float2(*(const __half2*)&u.w);
    f[0] = a.x; f[1] = a.y; f[2] = b.x; f[3] = b.y;
    f[4] = c.x; f[5] = c.y; f[6] = d.x; f[7] = d.y;
}

__global__ void attn_kernel(const float* __restrict__ att,
                            const float* __restrict__ bias) {
    __shared__ float bsum[C_OUT];
    __shared__ float bsq[C_OUT];
    int tid = threadIdx.x;
    if (tid < C_OUT) { bsum[tid] = 0.f; bsq[tid] = 0.f; }
    __syncthreads();

    int warp = (blockIdx.x * blockDim.x + tid) >> 5;
    int lane = tid & 31;

    if (warp < N_NODES) {
        int dst = warp;
        const float4* xr4 = ((const float4*)g_xr) + (long)dst * 64 + lane * 2;
        float4 r0 = xr4[0], r1 = xr4[1];
        float xrv[8] = {r0.x, r0.y, r0.z, r0.w, r1.x, r1.y, r1.z, r1.w};
        float4 a0 = ((const float4*)att)[lane * 2];
        float4 a1 = ((const float4*)att)[lane * 2 + 1];
        float attv[8] = {a0.x, a0.y, a0.z, a0.w, a1.x, a1.y, a1.z, a1.w};

        float m = -1e30f, denom = 0.f;
        float acc[8] = {0.f, 0.f, 0.f, 0.f, 0.f, 0.f, 0.f, 0.f};

        const int e0 = g_offsets[dst], e1 = g_offsets[dst + 1];
        int e = e0;
        const int nq = (e1 - e0) >> 3;

        for (int itq = 0; itq < nq; itq++, e += 8) {
            uint4 U[8];
#pragma unroll
            for (int u = 0; u < 8; u++) {
                int s = g_src_sorted[e + u];
                U[u] = *(((const uint4*)(g_xlh + (long)s * HC)) + lane);
            }
            float p[8];
#pragma unroll
            for (int u = 0; u < 8; u++) {
                float xlv[8];
                unpack8(U[u], xlv);
                float pp = 0.f;
#pragma unroll
                for (int j = 0; j < 8; j++) {
                    float t = xlv[j] + xrv[j];
                    t = (t > 0.f) ? t : NEG_SLOPE * t;
                    pp = fmaf(attv[j], t, pp);
                }
                p[u] = pp;
            }
#pragma unroll
            for (int u = 0; u < 8; u++) p[u] += __shfl_xor_sync(0xffffffffu, p[u], 4);
#pragma unroll
            for (int u = 0; u < 8; u++) p[u] += __shfl_xor_sync(0xffffffffu, p[u], 2);
#pragma unroll
            for (int u = 0; u < 8; u++) p[u] += __shfl_xor_sync(0xffffffffu, p[u], 1);
#pragma unroll
            for (int u = 0; u < 8; u++) {
                float mn = fmaxf(m, p[u]);
                float sc = __expf(m - mn);
                float w  = __expf(p[u] - mn);
                m = mn;
                denom = fmaf(denom, sc, w);
                float xlv[8];
                unpack8(U[u], xlv);
#pragma unroll
                for (int j = 0; j < 8; j++) acc[j] = fmaf(acc[j], sc, w * xlv[j]);
            }
        }
        for (; e < e1; e++) {
            int s = g_src_sorted[e];
            uint4 U = *(((const uint4*)(g_xlh + (long)s * HC)) + lane);
            float xlv[8];
            unpack8(U, xlv);
            float pp = 0.f;
#pragma unroll
            for (int j = 0; j < 8; j++) {
                float t = xlv[j] + xrv[j];
                t = (t > 0.f) ? t : NEG_SLOPE * t;
                pp = fmaf(attv[j], t, pp);
            }
            pp += __shfl_xor_sync(0xffffffffu, pp, 4);
            pp += __shfl_xor_sync(0xffffffffu, pp, 2);
            pp += __shfl_xor_sync(0xffffffffu, pp, 1);
            float mn = fmaxf(m, pp);
            float sc = __expf(m - mn);
            float w  = __expf(pp - mn);
            m = mn;
            denom = fmaf(denom, sc, w);
#pragma unroll
            for (int j = 0; j < 8; j++) acc[j] = fmaf(acc[j], sc, w * xlv[j]);
        }

        float inv = 1.f / (denom + 1e-16f);
        float v[8];
#pragma unroll
        for (int j = 0; j < 8; j++) v[j] = acc[j] * inv;
#pragma unroll
        for (int j = 0; j < 8; j++) {
            v[j] += __shfl_xor_sync(0xffffffffu, v[j], 8);
            v[j] += __shfl_xor_sync(0xffffffffu, v[j], 16);
        }
        if (lane < 8) {
#pragma unroll
            for (int j = 0; j < 8; j++) {
                int c = lane * 8 + j;
                float o = 0.25f * v[j] + bias[c];
                g_out[(long)dst * C_OUT + c] = o;
                atomicAdd(&bsum[c], o);
                atomicAdd(&bsq[c], o * o);
            }
        }
    }
    __syncthreads();
    if (tid < C_OUT) {
        atomicAdd(&g_sum[tid], bsum[tid]);
        atomicAdd(&g_sumsq[tid], bsq[tid]);
    }
}

// ---------------- GraphNorm ----------------
__global__ void finalize_kernel(const float* __restrict__ gw,
                                const float* __restrict__ gms) {
    int c = threadIdx.x;
    const float invN = 1.f / (float)N_NODES;
    float mu  = g_sum[c] * invN;
    float msq = g_sumsq[c] * invN;
    float a   = gms[c];
    float var = msq - 2.f * a * mu * mu + a * a * mu * mu;
    g_scale[c] = gw[c] * rsqrtf(var + 1e-5f);
    g_shift[c] = a * mu;
}

__global__ void norm_kernel(const float* __restrict__ gb,
                            float* __restrict__ out) {
    int i = blockIdx.x * blockDim.x + threadIdx.x;
    const int total = N_NODES * C_OUT / 4;
    if (i >= total) return;
    float4 v = ((const float4*)g_out)[i];
    int c = (i & 15) * 4;
    v.x = g_scale[c + 0] * (v.x - g_shift[c + 0]) + gb[c + 0];
    v.y = g_scale[c + 1] * (v.y - g_shift[c + 1]) + gb[c + 1];
    v.z = g_scale[c + 2] * (v.z - g_shift[c + 2]) + gb[c + 2];
    v.w = g_scale[c + 3] * (v.w - g_shift[c + 3]) + gb[c + 3];
    ((float4*)out)[i] = v;
}

// ---------------- launch ----------------
extern "C" void kernel_launch(void* const* d_in, const int* in_sizes, int n_in,
                              void* d_out, int out_size) {
    const float* X    = (const float*)d_in[0];
    const int*   E    = (const int*)  d_in[1];
    const float* Wl   = (const float*)d_in[2];
    const float* Wr   = (const float*)d_in[3];
    const float* att  = (const float*)d_in[4];
    const float* bias = (const float*)d_in[5];
    const float* gw   = (const float*)d_in[6];
    const float* gb   = (const float*)d_in[7];
    const float* gms  = (const float*)d_in[8];
    float* out = (float*)d_out;

    cudaFuncSetAttribute(gemm_mma_kernel, cudaFuncAttributeMaxDynamicSharedMemorySize, GSMEM);

    convx_kernel<<<(N_PAD * IN_F / 4 + 255) / 256, 256>>>(X);
    convb_kernel<<<(512 * IN_F + 255) / 256, 256>>>(Wl, Wr);
    gemm_mma_kernel<<<dim3(4, N_PAD / 128), 256, GSMEM>>>();
    hist_kernel<<<(ET + 255) / 256, 256>>>(E);
    scan1_kernel<<<NB_SCAN, 1024>>>();
    scan2_kernel<<<1, 64>>>();
    scan3_kernel<<<NB_SCAN, 1024>>>();
    scatter_kernel<<<(ET + 255) / 256, 256>>>(E);
    attn_kernel<<<(N_NODES + 7) / 8, 256>>>(att, bias);
    finalize_kernel<<<1, C_OUT>>>(gw, gms);
    norm_kernel<<<(N_NODES * C_OUT / 4 + 255) / 256, 256>>>(gb, out);
}

// round 14
// speedup vs baseline: 1.1970x; 1.1970x over previous
#include <cuda_runtime.h>
#include <cuda_fp16.h>
#include <cstdint>
#include <math.h>

#define N_NODES 50000
#define N_PAD   50048          // padded to multiple of 128 for GEMM tiles
#define E_RAW   800000
#define ET      (E_RAW + N_NODES)
#define IN_F    256
#define HC      256            // HEADS * OUT_F
#define C_OUT   64
#define NEG_SLOPE 0.2f
#define NB_SCAN 49             // ceil(50000/1024)

// ---- scratch (static __device__ arrays; no runtime allocation) ----
__device__ __align__(16) __half g_xlh[N_NODES * HC];   // xl in fp16 (attn gathers this)
__device__ float g_xr[N_NODES * HC];
__device__ float g_out[N_NODES * C_OUT];
__device__ int   g_counts[N_NODES];
__device__ int   g_rank[ET];
__device__ int   g_offsets[N_NODES + 1];
__device__ int   g_src_sorted[ET];
__device__ int   g_bsum[64];
__device__ int   g_boff[64];
__device__ float g_sum[C_OUT];
__device__ float g_sumsq[C_OUT];
__device__ float g_scale[C_OUT];
__device__ float g_shift[C_OUT];
// fp16 operands
__device__ __align__(16) __half g_Xh[N_PAD * IN_F];
__device__ __align__(16) __half g_Bh[512 * IN_F];   // [n][k]; n<256: Wl col, else Wr

// ---------------- helpers ----------------
__device__ __forceinline__ uint32_t smem_u32(const void* p) {
    uint32_t a;
    asm("{ .reg .u64 t; cvta.to.shared.u64 t, %1; cvt.u32.u64 %0, t; }" : "=r"(a) : "l"(p));
    return a;
}
__device__ __forceinline__ void cp16(uint32_t s, const void* g) {
    asm volatile("cp.async.cg.shared.global [%0], [%1], 16;" :: "r"(s), "l"(g));
}
#define CP_COMMIT() asm volatile("cp.async.commit_group;" ::: "memory")
#define CP_WAIT1()  asm volatile("cp.async.wait_group 1;" ::: "memory")
#define CP_WAIT0()  asm volatile("cp.async.wait_group 0;" ::: "memory")

__device__ __forceinline__ void mma_fp16(float* d, const uint32_t* a, const uint32_t* b) {
    asm volatile(
        "mma.sync.aligned.m16n8k16.row.col.f32.f16.f16.f32 "
        "{%0,%1,%2,%3}, {%4,%5,%6,%7}, {%8,%9}, {%0,%1,%2,%3};"
        : "+f"(d[0]), "+f"(d[1]), "+f"(d[2]), "+f"(d[3])
        : "r"(a[0]), "r"(a[1]), "r"(a[2]), "r"(a[3]), "r"(b[0]), "r"(b[1]));
}

// ---------------- fp16 conversion (fused with pad) ----------------
__global__ void convx_kernel(const float* __restrict__ X) {
    int i = blockIdx.x * blockDim.x + threadIdx.x;
    const int real = N_NODES * IN_F / 4;
    const int total = N_PAD * IN_F / 4;
    if (i >= total) return;
    __half h[4];
    if (i < real) {
        float4 v = ((const float4*)X)[i];
        h[0] = __float2half_rn(v.x); h[1] = __float2half_rn(v.y);
        h[2] = __float2half_rn(v.z); h[3] = __float2half_rn(v.w);
    } else {
        h[0] = h[1] = h[2] = h[3] = __float2half_rn(0.f);
    }
    ((uint2*)g_Xh)[i] = *(uint2*)h;
}

// convb + zero scratch fused
__global__ void convb_kernel(const float* __restrict__ Wl, const float* __restrict__ Wr) {
    int i = blockIdx.x * blockDim.x + threadIdx.x;   // over 512*256 = 131072
    if (i < N_NODES) g_counts[i] = 0;
    if (i < C_OUT)   { g_sum[i] = 0.f; g_sumsq[i] = 0.f; }
    if (i >= 512 * IN_F) return;
    int n = i >> 8, k = i & 255;
    const float* W = (n < 256) ? Wl : Wr;
    g_Bh[n * IN_F + k] = __float2half_rn(W[k * 256 + (n & 255)]);
}

// ---------------- mma.sync GEMM: Y[50000,512] = X @ [Wl|Wr] ----------------
// grid(4, 391). pure fp16 operands, fp32 accum, cp.async depth-2, scalar
// conflict-free LDS fragment loads. bx<2 -> xl (fp16 out); bx>=2 -> xr (fp32).
#define LDB   40               // padded k-stride (halfs) -> conflict-free LDS
#define TSZ   (128 * LDB)      // one operand tile, elems (5120)
#define BUFSZ (2 * TSZ)        // Ah | Bh
#define GSMEM (2 * BUFSZ * 2)  // bytes: 40960

__global__ void __launch_bounds__(256) gemm_mma_kernel() {
    extern __shared__ __align__(16) char dsm[];
    __half* sm = (__half*)dsm;
    uint32_t sb = smem_u32(dsm);

    const int tid = threadIdx.x;
    const int wid = tid >> 5, lane = tid & 31;
    const int wm = wid & 3, wn = wid >> 2;          // 4 warps on M, 2 on N
    const int q = lane >> 2, c2 = (lane & 3) * 2;
    const int bx = blockIdx.x, by = blockIdx.y;
    const int rowG = by * 128;

    float acc[2][8][4];
#pragma unroll
    for (int mt = 0; mt < 2; mt++)
#pragma unroll
        for (int nt = 0; nt < 8; nt++)
#pragma unroll
            for (int j = 0; j < 4; j++) acc[mt][nt][j] = 0.f;

    auto prefetch = [&](int c, int b) {
        const int k0 = c * 32;
        const uint32_t base = sb + b * (BUFSZ * 2);
#pragma unroll
        for (int i = 0; i < 2; i++) {
            int idx = tid + i * 256;
            int r = idx >> 2, seg = idx & 3;
            uint32_t off = (r * LDB + seg * 8) * 2;
            long ga = (long)(rowG + r) * IN_F + k0 + seg * 8;
            long gb = (long)(bx * 128 + r) * IN_F + k0 + seg * 8;
            cp16(base + off,           g_Xh + ga);
            cp16(base + TSZ * 2 + off, g_Bh + gb);
        }
        CP_COMMIT();
    };

    prefetch(0, 0);
    for (int c = 0; c < 8; c++) {
        if (c < 7) { prefetch(c + 1, (c + 1) & 1); CP_WAIT1(); }
        else       { CP_WAIT0(); }
        __syncthreads();

        const __half* Ah = sm + (c & 1) * BUFSZ;
        const __half* Bh = Ah + TSZ;

#pragma unroll
        for (int ks = 0; ks < 2; ks++) {
            const int kk = ks * 16;
            uint32_t ah[2][4];
#pragma unroll
            for (int mt = 0; mt < 2; mt++) {
                int rb = wm * 32 + mt * 16;
                ah[mt][0] = *(const uint32_t*)(Ah + (rb + q) * LDB + kk + c2);
                ah[mt][1] = *(const uint32_t*)(Ah + (rb + q + 8) * LDB + kk + c2);
                ah[mt][2] = *(const uint32_t*)(Ah + (rb + q) * LDB + kk + c2 + 8);
                ah[mt][3] = *(const uint32_t*)(Ah + (rb + q + 8) * LDB + kk + c2 + 8);
            }
            uint32_t bh[8][2];
#pragma unroll
            for (int nt = 0; nt < 8; nt++) {
                int nb = wn * 64 + nt * 8;
                bh[nt][0] = *(const uint32_t*)(Bh + (nb + q) * LDB + kk + c2);
                bh[nt][1] = *(const uint32_t*)(Bh + (nb + q) * LDB + kk + c2 + 8);
            }
#pragma unroll
            for (int mt = 0; mt < 2; mt++)
#pragma unroll
                for (int nt = 0; nt < 8; nt++)
                    mma_fp16(acc[mt][nt], ah[mt], bh[nt]);
        }
        __syncthreads();
    }

    const int colBase = (bx & 1) * 128;
    if (bx < 2) {   // xl -> fp16
#pragma unroll
        for (int mt = 0; mt < 2; mt++) {
            int r0 = rowG + wm * 32 + mt * 16 + q;
#pragma unroll
            for (int nt = 0; nt < 8; nt++) {
                int col = colBase + wn * 64 + nt * 8 + c2;
                if (r0 < N_NODES)
                    *(__half2*)(g_xlh + (long)r0 * HC + col) =
                        __floats2half2_rn(acc[mt][nt][0], acc[mt][nt][1]);
                if (r0 + 8 < N_NODES)
                    *(__half2*)(g_xlh + (long)(r0 + 8) * HC + col) =
                        __floats2half2_rn(acc[mt][nt][2], acc[mt][nt][3]);
            }
        }
    } else {        // xr -> fp32
#pragma unroll
        for (int mt = 0; mt < 2; mt++) {
            int r0 = rowG + wm * 32 + mt * 16 + q;
#pragma unroll
            for (int nt = 0; nt < 8; nt++) {
                int col = colBase + wn * 64 + nt * 8 + c2;
                if (r0 < N_NODES)
                    *(float2*)(g_xr + (long)r0 * HC + col) = make_float2(acc[mt][nt][0], acc[mt][nt][1]);
                if (r0 + 8 < N_NODES)
                    *(float2*)(g_xr + (long)(r0 + 8) * HC + col) = make_float2(acc[mt][nt][2], acc[mt][nt][3]);
            }
        }
    }
}

// ---------------- CSR build (dst-sorted) ----------------
// hist records each edge's arrival rank; scatter then needs no second atomic.
__global__ void hist_kernel(const int* __restrict__ E) {
    int i = blockIdx.x * blockDim.x + threadIdx.x;
    if (i >= ET) return;
    int d = (i < E_RAW) ? E[E_RAW + i] : (i - E_RAW);
    g_rank[i] = atomicAdd(&g_counts[d], 1);
}

__global__ void scan1_kernel() {
    __shared__ int sh[1024];
    int b = blockIdx.x, t = threadIdx.x;
    int i = b * 1024 + t;
    int v = (i < N_NODES) ? g_counts[i] : 0;
    sh[t] = v;
    __syncthreads();
    for (int off = 1; off < 1024; off <<= 1) {
        int add = (t >= off) ? sh[t - off] : 0;
        __syncthreads();
        sh[t] += add;
        __syncthreads();
    }
    if (i < N_NODES) g_offsets[i + 1] = sh[t];
    if (t == 1023) g_bsum[b] = sh[1023];
}

__global__ void scan2_kernel() {
    __shared__ int sh[64];
    int t = threadIdx.x;
    int v = (t < NB_SCAN) ? g_bsum[t] : 0;
    sh[t] = v;
    __syncthreads();
    for (int off = 1; off < 64; off <<= 1) {
        int add = (t >= off) ? sh[t - off] : 0;
        __syncthreads();
        sh[t] += add;
        __syncthreads();
    }
    if (t < NB_SCAN) g_boff[t] = sh[t] - v;
}

__global__ void scan3_kernel() {
    int b = blockIdx.x;
    int i = b * 1024 + threadIdx.x;
    if (i < N_NODES) g_offsets[i + 1] += g_boff[b];
    if (i == 0) g_offsets[0] = 0;
}

__global__ void scatter_kernel(const int* __restrict__ E) {
    int i = blockIdx.x * blockDim.x + threadIdx.x;
    if (i >= ET) return;
    int s, d;
    if (i < E_RAW) { s = E[i]; d = E[E_RAW + i]; }
    else           { s = d = i - E_RAW; }
    g_src_sorted[g_offsets[d] + g_rank[i]] = s;
}

// ---------------- attention: one warp per destination node ----------------
// xl gathered as fp16 (one uint4 = the lane's 8 channels). 4-edge pipeline.
__device__ __forceinline__ void unpack8(const uint4& u, float* f) {
    float2 a = __half22float2(*(const __half2*)&u.x);
    float2 b = __half22float2(*(const __half2*)&u.y);
    float2 c = __half22float2(*(const __half2*)&u.z);
    float2 d = __half22float2(*(const __half2*)&u.w);
    f[0] = a.x; f[1] = a.y; f[2] = b.x; f[3] = b.y;
    f[4] = c.x; f[5] = c.y; f[6] = d.x; f[7] = d.y;
}

__global__ void attn_kernel(const float* __restrict__ att,
                            const float* __restrict__ bias) {
    __shared__ float bsum[C_OUT];
    __shared__ float bsq[C_OUT];
    int tid = threadIdx.x;
    if (tid < C_OUT) { bsum[tid] = 0.f; bsq[tid] = 0.f; }
    __syncthreads();

    int warp = (blockIdx.x * blockDim.x + tid) >> 5;
    int lane = tid & 31;

    if (warp < N_NODES) {
        int dst = warp;
        const float4* xr4 = ((const float4*)g_xr) + (long)dst * 64 + lane * 2;
        float4 r0 = xr4[0], r1 = xr4[1];
        float xrv[8] = {r0.x, r0.y, r0.z, r0.w, r1.x, r1.y, r1.z, r1.w};
        float4 a0 = ((const float4*)att)[lane * 2];
        float4 a1 = ((const float4*)att)[lane * 2 + 1];
        float attv[8] = {a0.x, a0.y, a0.z, a0.w, a1.x, a1.y, a1.z, a1.w};

        float m = -1e30f, denom = 0.f;
        float acc[8] = {0.f, 0.f, 0.f, 0.f, 0.f, 0.f, 0.f, 0.f};

        const int e0 = g_offsets[dst], e1 = g_offsets[dst + 1];
        int e = e0;
        const int nq = (e1 - e0) >> 2;

        for (int itq = 0; itq < nq; itq++, e += 4) {
            uint4 U[4];
#pragma unroll
            for (int u = 0; u < 4; u++) {
                int s = g_src_sorted[e + u];
                U[u] = *(((const uint4*)(g_xlh + (long)s * HC)) + lane);
            }
            float xl4v[4][8];
            float p[4];
#pragma unroll
            for (int u = 0; u < 4; u++) {
                unpack8(U[u], xl4v[u]);
                float pp = 0.f;
#pragma unroll
                for (int j = 0; j < 8; j++) {
                    float t = xl4v[u][j] + xrv[j];
                    t = (t > 0.f) ? t : NEG_SLOPE * t;
                    pp = fmaf(attv[j], t, pp);
                }
                p[u] = pp;
            }
#pragma unroll
            for (int u = 0; u < 4; u++) p[u] += __shfl_xor_sync(0xffffffffu, p[u], 4);
#pragma unroll
            for (int u = 0; u < 4; u++) p[u] += __shfl_xor_sync(0xffffffffu, p[u], 2);
#pragma unroll
            for (int u = 0; u < 4; u++) p[u] += __shfl_xor_sync(0xffffffffu, p[u], 1);
#pragma unroll
            for (int u = 0; u < 4; u++) {
                float mn = fmaxf(m, p[u]);
                float sc = __expf(m - mn);
                float w  = __expf(p[u] - mn);
                m = mn;
                denom = fmaf(denom, sc, w);
#pragma unroll
                for (int j = 0; j < 8; j++) acc[j] = fmaf(acc[j], sc, w * xl4v[u][j]);
            }
        }
        for (; e < e1; e++) {
            int s = g_src_sorted[e];
            uint4 U = *(((const uint4*)(g_xlh + (long)s * HC)) + lane);
            float xlv[8];
            unpack8(U, xlv);
            float pp = 0.f;
#pragma unroll
            for (int j = 0; j < 8; j++) {
                float t = xlv[j] + xrv[j];
                t = (t > 0.f) ? t : NEG_SLOPE * t;
                pp = fmaf(attv[j], t, pp);
            }
            pp += __shfl_xor_sync(0xffffffffu, pp, 4);
            pp += __shfl_xor_sync(0xffffffffu, pp, 2);
            pp += __shfl_xor_sync(0xffffffffu, pp, 1);
            float mn = fmaxf(m, pp);
            float sc = __expf(m - mn);
            float w  = __expf(pp - mn);
            m = mn;
            denom = fmaf(denom, sc, w);
#pragma unroll
            for (int j = 0; j < 8; j++) acc[j] = fmaf(acc[j], sc, w * xlv[j]);
        }

        float inv = 1.f / (denom + 1e-16f);
        float v[8];
#pragma unroll
        for (int j = 0; j < 8; j++) v[j] = acc[j] * inv;
#pragma unroll
        for (int j = 0; j < 8; j++) {
            v[j] += __shfl_xor_sync(0xffffffffu, v[j], 8);
            v[j] += __shfl_xor_sync(0xffffffffu, v[j], 16);
        }
        if (lane < 8) {
#pragma unroll
            for (int j = 0; j < 8; j++) {
                int c = lane * 8 + j;
                float o = 0.25f * v[j] + bias[c];
                g_out[(long)dst * C_OUT + c] = o;
                atomicAdd(&bsum[c], o);
                atomicAdd(&bsq[c], o * o);
            }
        }
    }
    __syncthreads();
    if (tid < C_OUT) {
        atomicAdd(&g_sum[tid], bsum[tid]);
        atomicAdd(&g_sumsq[tid], bsq[tid]);
    }
}

// ---------------- GraphNorm ----------------
__global__ void finalize_kernel(const float* __restrict__ gw,
                                const float* __restrict__ gms) {
    int c = threadIdx.x;
    const float invN = 1.f / (float)N_NODES;
    float mu  = g_sum[c] * invN;
    float msq = g_sumsq[c] * invN;
    float a   = gms[c];
    float var = msq - 2.f * a * mu * mu + a * a * mu * mu;
    g_scale[c] = gw[c] * rsqrtf(var + 1e-5f);
    g_shift[c] = a * mu;
}

__global__ void norm_kernel(const float* __restrict__ gb,
                            float* __restrict__ out) {
    int i = blockIdx.x * blockDim.x + threadIdx.x;
    const int total = N_NODES * C_OUT / 4;
    if (i >= total) return;
    float4 v = ((const float4*)g_out)[i];
    int c = (i & 15) * 4;
    v.x = g_scale[c + 0] * (v.x - g_shift[c + 0]) + gb[c + 0];
    v.y = g_scale[c + 1] * (v.y - g_shift[c + 1]) + gb[c + 1];
    v.z = g_scale[c + 2] * (v.z - g_shift[c + 2]) + gb[c + 2];
    v.w = g_scale[c + 3] * (v.w - g_shift[c + 3]) + gb[c + 3];
    ((float4*)out)[i] = v;
}

// ---------------- launch ----------------
extern "C" void kernel_launch(void* const* d_in, const int* in_sizes, int n_in,
                              void* d_out, int out_size) {
    const float* X    = (const float*)d_in[0];
    const int*   E    = (const int*)  d_in[1];
    const float* Wl   = (const float*)d_in[2];
    const float* Wr   = (const float*)d_in[3];
    const float* att  = (const float*)d_in[4];
    const float* bias = (const float*)d_in[5];
    const float* gw   = (const float*)d_in[6];
    const float* gb   = (const float*)d_in[7];
    const float* gms  = (const float*)d_in[8];
    float* out = (float*)d_out;

    cudaFuncSetAttribute(gemm_mma_kernel, cudaFuncAttributeMaxDynamicSharedMemorySize, GSMEM);

    convx_kernel<<<(N_PAD * IN_F / 4 + 255) / 256, 256>>>(X);
    convb_kernel<<<(512 * IN_F + 255) / 256, 256>>>(Wl, Wr);
    gemm_mma_kernel<<<dim3(4, N_PAD / 128), 256, GSMEM>>>();
    hist_kernel<<<(ET + 255) / 256, 256>>>(E);
    scan1_kernel<<<NB_SCAN, 1024>>>();
    scan2_kernel<<<1, 64>>>();
    scan3_kernel<<<NB_SCAN, 1024>>>();
    scatter_kernel<<<(ET + 255) / 256, 256>>>(E);
    attn_kernel<<<(N_NODES + 7) / 8, 256>>>(att, bias);
    finalize_kernel<<<1, C_OUT>>>(gw, gms);
    norm_kernel<<<(N_NODES * C_OUT / 4 + 255) / 256, 256>>>(gb, out);
}

// round 15
// speedup vs baseline: 1.2414x; 1.0371x over previous
#include <cuda_runtime.h>
#include <cuda_fp16.h>
#include <cstdint>
#include <math.h>

#define N_NODES 50000
#define N_PAD   50048          // padded to multiple of 128 for GEMM tiles
#define E_RAW   800000
#define ET      (E_RAW + N_NODES)   // 850000 (divisible by 4)
#define IN_F    256
#define HC      256            // HEADS * OUT_F
#define C_OUT   64
#define NEG_SLOPE 0.2f
#define NB_SCAN 49             // ceil(50000/1024)

// ---- scratch (static __device__ arrays; no runtime allocation) ----
__device__ __align__(16) __half g_xlh[N_NODES * HC];   // xl in fp16 (attn gathers this)
__device__ float g_xr[N_NODES * HC];
__device__ float g_out[N_NODES * C_OUT];
__device__ int   g_counts[N_NODES];
__device__ __align__(16) int g_rank[ET];
__device__ int   g_offsets[N_NODES + 1];   // local (per-1024-block) inclusive scans
__device__ int   g_src_sorted[ET];
__device__ int   g_bsum[64];
__device__ int   g_boff[64];
__device__ float g_sum[C_OUT];
__device__ float g_sumsq[C_OUT];
__device__ float g_scale[C_OUT];
__device__ float g_shift[C_OUT];
// fp16 operands
__device__ __align__(16) __half g_Xh[N_PAD * IN_F];
__device__ __align__(16) __half g_Bh[512 * IN_F];   // [n][k]; n<256: Wl col, else Wr

// final exclusive CSR offset of node j
__device__ __forceinline__ int final_off(int j) {
    return (j == 0) ? 0 : (g_offsets[j] + g_boff[(j - 1) >> 10]);
}

// ---------------- helpers ----------------
__device__ __forceinline__ uint32_t smem_u32(const void* p) {
    uint32_t a;
    asm("{ .reg .u64 t; cvta.to.shared.u64 t, %1; cvt.u32.u64 %0, t; }" : "=r"(a) : "l"(p));
    return a;
}
__device__ __forceinline__ void cp16(uint32_t s, const void* g) {
    asm volatile("cp.async.cg.shared.global [%0], [%1], 16;" :: "r"(s), "l"(g));
}
#define CP_COMMIT() asm volatile("cp.async.commit_group;" ::: "memory")
#define CP_WAIT1()  asm volatile("cp.async.wait_group 1;" ::: "memory")
#define CP_WAIT0()  asm volatile("cp.async.wait_group 0;" ::: "memory")

__device__ __forceinline__ void mma_fp16(float* d, const uint32_t* a, const uint32_t* b) {
    asm volatile(
        "mma.sync.aligned.m16n8k16.row.col.f32.f16.f16.f32 "
        "{%0,%1,%2,%3}, {%4,%5,%6,%7}, {%8,%9}, {%0,%1,%2,%3};"
        : "+f"(d[0]), "+f"(d[1]), "+f"(d[2]), "+f"(d[3])
        : "r"(a[0]), "r"(a[1]), "r"(a[2]), "r"(a[3]), "r"(b[0]), "r"(b[1]));
}

// ---------------- convb + zero scratch (runs FIRST: zeroes g_counts) ----------------
__global__ void convb_kernel(const float* __restrict__ Wl, const float* __restrict__ Wr) {
    int i = blockIdx.x * blockDim.x + threadIdx.x;   // over 512*256 = 131072
    if (i < N_NODES) g_counts[i] = 0;
    if (i < C_OUT)   { g_sum[i] = 0.f; g_sumsq[i] = 0.f; }
    if (i >= 512 * IN_F) return;
    int n = i >> 8, k = i & 255;
    const float* W = (n < 256) ? Wl : Wr;
    g_Bh[n * IN_F + k] = __float2half_rn(W[k * 256 + (n & 255)]);
}

// ---------------- fp16 conversion of X (+pad) fused with edge histogram ----------------
__global__ void convx_kernel(const float* __restrict__ X, const int* __restrict__ E) {
    int i = blockIdx.x * blockDim.x + threadIdx.x;

    // histogram part: 4 edges per thread (ET/4 = 212500 threads)
    if (i < ET / 4) {
        int4 d4;
        int base = i * 4;
        if (base < E_RAW) {
            d4 = *(const int4*)(E + E_RAW + base);     // 16B-aligned (E_RAW%4==0)
        } else {
            int b = base - E_RAW;
            d4 = make_int4(b, b + 1, b + 2, b + 3);    // self-loop dst
        }
        int4 r4;
        r4.x = atomicAdd(&g_counts[d4.x], 1);
        r4.y = atomicAdd(&g_counts[d4.y], 1);
        r4.z = atomicAdd(&g_counts[d4.z], 1);
        r4.w = atomicAdd(&g_counts[d4.w], 1);
        *(int4*)(g_rank + base) = r4;
    }

    // conversion part
    const int real = N_NODES * IN_F / 4;
    const int total = N_PAD * IN_F / 4;
    if (i >= total) return;
    __half h[4];
    if (i < real) {
        float4 v = ((const float4*)X)[i];
        h[0] = __float2half_rn(v.x); h[1] = __float2half_rn(v.y);
        h[2] = __float2half_rn(v.z); h[3] = __float2half_rn(v.w);
    } else {
        h[0] = h[1] = h[2] = h[3] = __float2half_rn(0.f);
    }
    ((uint2*)g_Xh)[i] = *(uint2*)h;
}

// ---------------- mma.sync GEMM: Y[50000,512] = X @ [Wl|Wr] ----------------
#define LDB   40               // padded k-stride (halfs) -> conflict-free LDS
#define TSZ   (128 * LDB)      // one operand tile, elems (5120)
#define BUFSZ (2 * TSZ)        // Ah | Bh
#define GSMEM (2 * BUFSZ * 2)  // bytes: 40960

__global__ void __launch_bounds__(256) gemm_mma_kernel() {
    extern __shared__ __align__(16) char dsm[];
    __half* sm = (__half*)dsm;
    uint32_t sb = smem_u32(dsm);

    const int tid = threadIdx.x;
    const int wid = tid >> 5, lane = tid & 31;
    const int wm = wid & 3, wn = wid >> 2;          // 4 warps on M, 2 on N
    const int q = lane >> 2, c2 = (lane & 3) * 2;
    const int bx = blockIdx.x, by = blockIdx.y;
    const int rowG = by * 128;

    float acc[2][8][4];
#pragma unroll
    for (int mt = 0; mt < 2; mt++)
#pragma unroll
        for (int nt = 0; nt < 8; nt++)
#pragma unroll
            for (int j = 0; j < 4; j++) acc[mt][nt][j] = 0.f;

    auto prefetch = [&](int c, int b) {
        const int k0 = c * 32;
        const uint32_t base = sb + b * (BUFSZ * 2);
#pragma unroll
        for (int i = 0; i < 2; i++) {
            int idx = tid + i * 256;
            int r = idx >> 2, seg = idx & 3;
            uint32_t off = (r * LDB + seg * 8) * 2;
            long ga = (long)(rowG + r) * IN_F + k0 + seg * 8;
            long gb = (long)(bx * 128 + r) * IN_F + k0 + seg * 8;
            cp16(base + off,           g_Xh + ga);
            cp16(base + TSZ * 2 + off, g_Bh + gb);
        }
        CP_COMMIT();
    };

    prefetch(0, 0);
    for (int c = 0; c < 8; c++) {
        if (c < 7) { prefetch(c + 1, (c + 1) & 1); CP_WAIT1(); }
        else       { CP_WAIT0(); }
        __syncthreads();

        const __half* Ah = sm + (c & 1) * BUFSZ;
        const __half* Bh = Ah + TSZ;

#pragma unroll
        for (int ks = 0; ks < 2; ks++) {
            const int kk = ks * 16;
            uint32_t ah[2][4];
#pragma unroll
            for (int mt = 0; mt < 2; mt++) {
                int rb = wm * 32 + mt * 16;
                ah[mt][0] = *(const uint32_t*)(Ah + (rb + q) * LDB + kk + c2);
                ah[mt][1] = *(const uint32_t*)(Ah + (rb + q + 8) * LDB + kk + c2);
                ah[mt][2] = *(const uint32_t*)(Ah + (rb + q) * LDB + kk + c2 + 8);
                ah[mt][3] = *(const uint32_t*)(Ah + (rb + q + 8) * LDB + kk + c2 + 8);
            }
            uint32_t bh[8][2];
#pragma unroll
            for (int nt = 0; nt < 8; nt++) {
                int nb = wn * 64 + nt * 8;
                bh[nt][0] = *(const uint32_t*)(Bh + (nb + q) * LDB + kk + c2);
                bh[nt][1] = *(const uint32_t*)(Bh + (nb + q) * LDB + kk + c2 + 8);
            }
#pragma unroll
            for (int mt = 0; mt < 2; mt++)
#pragma unroll
                for (int nt = 0; nt < 8; nt++)
                    mma_fp16(acc[mt][nt], ah[mt], bh[nt]);
        }
        __syncthreads();
    }

    const int colBase = (bx & 1) * 128;
    if (bx < 2) {   // xl -> fp16
#pragma unroll
        for (int mt = 0; mt < 2; mt++) {
            int r0 = rowG + wm * 32 + mt * 16 + q;
#pragma unroll
            for (int nt = 0; nt < 8; nt++) {
                int col = colBase + wn * 64 + nt * 8 + c2;
                if (r0 < N_NODES)
                    *(__half2*)(g_xlh + (long)r0 * HC + col) =
                        __floats2half2_rn(acc[mt][nt][0], acc[mt][nt][1]);
                if (r0 + 8 < N_NODES)
                    *(__half2*)(g_xlh + (long)(r0 + 8) * HC + col) =
                        __floats2half2_rn(acc[mt][nt][2], acc[mt][nt][3]);
            }
        }
    } else {        // xr -> fp32
#pragma unroll
        for (int mt = 0; mt < 2; mt++) {
            int r0 = rowG + wm * 32 + mt * 16 + q;
#pragma unroll
            for (int nt = 0; nt < 8; nt++) {
                int col = colBase + wn * 64 + nt * 8 + c2;
                if (r0 < N_NODES)
                    *(float2*)(g_xr + (long)r0 * HC + col) = make_float2(acc[mt][nt][0], acc[mt][nt][1]);
                if (r0 + 8 < N_NODES)
                    *(float2*)(g_xr + (long)(r0 + 8) * HC + col) = make_float2(acc[mt][nt][2], acc[mt][nt][3]);
            }
        }
    }
}

// ---------------- CSR scan (2 kernels; block offsets folded into consumers) ----------------
__global__ void scan1_kernel() {
    __shared__ int sh[1024];
    int b = blockIdx.x, t = threadIdx.x;
    int i = b * 1024 + t;
    int v = (i < N_NODES) ? g_counts[i] : 0;
    sh[t] = v;
    __syncthreads();
    for (int off = 1; off < 1024; off <<= 1) {
        int add = (t >= off) ? sh[t - off] : 0;
        __syncthreads();
        sh[t] += add;
        __syncthreads();
    }
    if (i < N_NODES) g_offsets[i + 1] = sh[t];
    if (t == 1023) g_bsum[b] = sh[1023];
}

__global__ void scan2_kernel() {
    __shared__ int sh[64];
    int t = threadIdx.x;
    int v = (t < NB_SCAN) ? g_bsum[t] : 0;
    sh[t] = v;
    __syncthreads();
    for (int off = 1; off < 64; off <<= 1) {
        int add = (t >= off) ? sh[t - off] : 0;
        __syncthreads();
        sh[t] += add;
        __syncthreads();
    }
    if (t < NB_SCAN) g_boff[t] = sh[t] - v;
    if (t == 0) g_offsets[0] = 0;
}

__global__ void scatter_kernel(const int* __restrict__ E) {
    int g = blockIdx.x * blockDim.x + threadIdx.x;
    if (g >= ET / 4) return;
    int base = g * 4;
    int4 s4, d4;
    if (base < E_RAW) {
        s4 = *(const int4*)(E + base);
        d4 = *(const int4*)(E + E_RAW + base);
    } else {
        int b = base - E_RAW;
        s4 = d4 = make_int4(b, b + 1, b + 2, b + 3);
    }
    int4 r4 = *(const int4*)(g_rank + base);
    g_src_sorted[final_off(d4.x) + r4.x] = s4.x;
    g_src_sorted[final_off(d4.y) + r4.y] = s4.y;
    g_src_sorted[final_off(d4.z) + r4.z] = s4.z;
    g_src_sorted[final_off(d4.w) + r4.w] = s4.w;
}

// ---------------- attention: one warp per destination node ----------------
// xl gathered as fp16 (one uint4 = the lane's 8 channels). 4-edge group-max softmax.
__device__ __forceinline__ void unpack8(const uint4& u, float* f) {
    float2 a = __half22float2(*(const __half2*)&u.x);
    float2 b = __half22float2(*(const __half2*)&u.y);
    float2 c = __half22float2(*(const __half2*)&u.z);
    float2 d = __half22float2(*(const __half2*)&u.w);
    f[0] = a.x; f[1] = a.y; f[2] = b.x; f[3] = b.y;
    f[4] = c.x; f[5] = c.y; f[6] = d.x; f[7] = d.y;
}

__global__ void attn_kernel(const float* __restrict__ att,
                            const float* __restrict__ bias) {
    __shared__ float bsum[C_OUT];
    __shared__ float bsq[C_OUT];
    int tid = threadIdx.x;
    if (tid < C_OUT) { bsum[tid] = 0.f; bsq[tid] = 0.f; }
    __syncthreads();

    int warp = (blockIdx.x * blockDim.x + tid) >> 5;
    int lane = tid & 31;

    if (warp < N_NODES) {
        int dst = warp;
        const float4* xr4 = ((const float4*)g_xr) + (long)dst * 64 + lane * 2;
        float4 r0 = xr4[0], r1 = xr4[1];
        float xrv[8] = {r0.x, r0.y, r0.z, r0.w, r1.x, r1.y, r1.z, r1.w};
        float4 a0 = ((const float4*)att)[lane * 2];
        float4 a1 = ((const float4*)att)[lane * 2 + 1];
        float attv[8] = {a0.x, a0.y, a0.z, a0.w, a1.x, a1.y, a1.z, a1.w};

        float m = -1e30f, denom = 0.f;
        float acc[8] = {0.f, 0.f, 0.f, 0.f, 0.f, 0.f, 0.f, 0.f};

        const int e0 = final_off(dst), e1 = final_off(dst + 1);
        int e = e0;
        const int nq = (e1 - e0) >> 2;

        for (int itq = 0; itq < nq; itq++, e += 4) {
            uint4 U[4];
#pragma unroll
            for (int u = 0; u < 4; u++) {
                int s = g_src_sorted[e + u];
                U[u] = *(((const uint4*)(g_xlh + (long)s * HC)) + lane);
            }
            float xl4v[4][8];
            float p[4];
#pragma unroll
            for (int u = 0; u < 4; u++) {
                unpack8(U[u], xl4v[u]);
                float pp = 0.f;
#pragma unroll
                for (int j = 0; j < 8; j++) {
                    float t = xl4v[u][j] + xrv[j];
                    t = (t > 0.f) ? t : NEG_SLOPE * t;
                    pp = fmaf(attv[j], t, pp);
                }
                p[u] = pp;
            }
#pragma unroll
            for (int u = 0; u < 4; u++) p[u] += __shfl_xor_sync(0xffffffffu, p[u], 4);
#pragma unroll
            for (int u = 0; u < 4; u++) p[u] += __shfl_xor_sync(0xffffffffu, p[u], 2);
#pragma unroll
            for (int u = 0; u < 4; u++) p[u] += __shfl_xor_sync(0xffffffffu, p[u], 1);

            // group-max online softmax: one rescale + 5 exps per 4 edges (exact)
            float gm = fmaxf(fmaxf(p[0], p[1]), fmaxf(p[2], p[3]));
            float mn = fmaxf(m, gm);
            float sc = __expf(m - mn);
            float w0 = __expf(p[0] - mn);
            float w1 = __expf(p[1] - mn);
            float w2 = __expf(p[2] - mn);
            float w3 = __expf(p[3] - mn);
            m = mn;
            denom = fmaf(denom, sc, (w0 + w1) + (w2 + w3));
#pragma unroll
            for (int j = 0; j < 8; j++) {
                float t = w0 * xl4v[0][j];
                t = fmaf(w1, xl4v[1][j], t);
                t = fmaf(w2, xl4v[2][j], t);
                t = fmaf(w3, xl4v[3][j], t);
                acc[j] = fmaf(acc[j], sc, t);
            }
        }
        for (; e < e1; e++) {
            int s = g_src_sorted[e];
            uint4 U = *(((const uint4*)(g_xlh + (long)s * HC)) + lane);
            float xlv[8];
            unpack8(U, xlv);
            float pp = 0.f;
#pragma unroll
            for (int j = 0; j < 8; j++) {
                float t = xlv[j] + xrv[j];
                t = (t > 0.f) ? t : NEG_SLOPE * t;
                pp = fmaf(attv[j], t, pp);
            }
            pp += __shfl_xor_sync(0xffffffffu, pp, 4);
            pp += __shfl_xor_sync(0xffffffffu, pp, 2);
            pp += __shfl_xor_sync(0xffffffffu, pp, 1);
            float mn = fmaxf(m, pp);
            float sc = __expf(m - mn);
            float w  = __expf(pp - mn);
            m = mn;
            denom = fmaf(denom, sc, w);
#pragma unroll
            for (int j = 0; j < 8; j++) acc[j] = fmaf(acc[j], sc, w * xlv[j]);
        }

        float inv = 1.f / (denom + 1e-16f);
        float v[8];
#pragma unroll
        for (int j = 0; j < 8; j++) v[j] = acc[j] * inv;
#pragma unroll
        for (int j = 0; j < 8; j++) {
            v[j] += __shfl_xor_sync(0xffffffffu, v[j], 8);
            v[j] += __shfl_xor_sync(0xffffffffu, v[j], 16);
        }
        if (lane < 8) {
#pragma unroll
            for (int j = 0; j < 8; j++) {
                int c = lane * 8 + j;
                float o = 0.25f * v[j] + bias[c];
                g_out[(long)dst * C_OUT + c] = o;
                atomicAdd(&bsum[c], o);
                atomicAdd(&bsq[c], o * o);
            }
        }
    }
    __syncthreads();
    if (tid < C_OUT) {
        atomicAdd(&g_sum[tid], bsum[tid]);
        atomicAdd(&g_sumsq[tid], bsq[tid]);
    }
}

// ---------------- GraphNorm ----------------
__global__ void finalize_kernel(const float* __restrict__ gw,
                                const float* __restrict__ gms) {
    int c = threadIdx.x;
    const float invN = 1.f / (float)N_NODES;
    float mu  = g_sum[c] * invN;
    float msq = g_sumsq[c] * invN;
    float a   = gms[c];
    float var = msq - 2.f * a * mu * mu + a * a * mu * mu;
    g_scale[c] = gw[c] * rsqrtf(var + 1e-5f);
    g_shift[c] = a * mu;
}

__global__ void norm_kernel(const float* __restrict__ gb,
                            float* __restrict__ out) {
    int i = blockIdx.x * blockDim.x + threadIdx.x;
    const int total = N_NODES * C_OUT / 4;
    if (i >= total) return;
    float4 v = ((const float4*)g_out)[i];
    int c = (i & 15) * 4;
    v.x = g_scale[c + 0] * (v.x - g_shift[c + 0]) + gb[c + 0];
    v.y = g_scale[c + 1] * (v.y - g_shift[c + 1]) + gb[c + 1];
    v.z = g_scale[c + 2] * (v.z - g_shift[c + 2]) + gb[c + 2];
    v.w = g_scale[c + 3] * (v.w - g_shift[c + 3]) + gb[c + 3];
    ((float4*)out)[i] = v;
}

// ---------------- launch ----------------
extern "C" void kernel_launch(void* const* d_in, const int* in_sizes, int n_in,
                              void* d_out, int out_size) {
    const float* X    = (const float*)d_in[0];
    const int*   E    = (const int*)  d_in[1];
    const float* Wl   = (const float*)d_in[2];
    const float* Wr   = (const float*)d_in[3];
    const float* att  = (const float*)d_in[4];
    const float* bias = (const float*)d_in[5];
    const float* gw   = (const float*)d_in[6];
    const float* gb   = (const float*)d_in[7];
    const float* gms  = (const float*)d_in[8];
    float* out = (float*)d_out;

    cudaFuncSetAttribute(gemm_mma_kernel, cudaFuncAttributeMaxDynamicSharedMemorySize, GSMEM);

    convb_kernel<<<(512 * IN_F + 255) / 256, 256>>>(Wl, Wr);          // zeroes counts first
    convx_kernel<<<(N_PAD * IN_F / 4 + 255) / 256, 256>>>(X, E);      // + edge histogram
    gemm_mma_kernel<<<dim3(4, N_PAD / 128), 256, GSMEM>>>();
    scan1_kernel<<<NB_SCAN, 1024>>>();
    scan2_kernel<<<1, 64>>>();
    scatter_kernel<<<(ET / 4 + 255) / 256, 256>>>(E);
    attn_kernel<<<(N_NODES + 7) / 8, 256>>>(att, bias);
    finalize_kernel<<<1, C_OUT>>>(gw, gms);
    norm_kernel<<<(N_NODES * C_OUT / 4 + 255) / 256, 256>>>(gb, out);
}

// round 16
// speedup vs baseline: 1.2700x; 1.0230x over previous
#include <cuda_runtime.h>
#include <cuda_fp16.h>
#include <cstdint>
#include <math.h>

#define N_NODES 50000
#define N_PAD   50048          // padded to multiple of 128 for GEMM tiles
#define E_RAW   800000
#define ET      (E_RAW + N_NODES)   // 850000 (divisible by 4)
#define IN_F    256
#define HC      256            // HEADS * OUT_F
#define C_OUT   64
#define NEG_SLOPE 0.2f
#define NB_SCAN 49             // ceil(50000/1024)

// ---- scratch (static __device__ arrays; no runtime allocation) ----
__device__ __align__(16) __half g_xlh[N_NODES * HC];   // xl in fp16 (attn gathers this)
__device__ float g_xr[N_NODES * HC];
__device__ float g_out[N_NODES * C_OUT];
__device__ int   g_counts[N_NODES];
__device__ __align__(16) int g_rank[ET];
__device__ int   g_offsets[N_NODES + 1];   // local (per-1024-block) inclusive scans
__device__ int   g_src_sorted[ET];
__device__ int   g_bsum[64];
__device__ int   g_boff[64];
__device__ float g_sum[C_OUT];
__device__ float g_sumsq[C_OUT];
__device__ float g_scale[C_OUT];
__device__ float g_shift[C_OUT];
// fp16 operands
__device__ __align__(16) __half g_Xh[N_PAD * IN_F];
__device__ __align__(16) __half g_Bh[512 * IN_F];   // [n][k]; n<256: Wl col, else Wr

// final exclusive CSR offset of node j
__device__ __forceinline__ int final_off(int j) {
    return (j == 0) ? 0 : (g_offsets[j] + g_boff[(j - 1) >> 10]);
}

// ---------------- helpers ----------------
__device__ __forceinline__ uint32_t smem_u32(const void* p) {
    uint32_t a;
    asm("{ .reg .u64 t; cvta.to.shared.u64 t, %1; cvt.u32.u64 %0, t; }" : "=r"(a) : "l"(p));
    return a;
}
__device__ __forceinline__ void cp16(uint32_t s, const void* g) {
    asm volatile("cp.async.cg.shared.global [%0], [%1], 16;" :: "r"(s), "l"(g));
}
#define CP_COMMIT() asm volatile("cp.async.commit_group;" ::: "memory")
#define CP_WAIT1()  asm volatile("cp.async.wait_group 1;" ::: "memory")
#define CP_WAIT0()  asm volatile("cp.async.wait_group 0;" ::: "memory")

__device__ __forceinline__ void mma_fp16(float* d, const uint32_t* a, const uint32_t* b) {
    asm volatile(
        "mma.sync.aligned.m16n8k16.row.col.f32.f16.f16.f32 "
        "{%0,%1,%2,%3}, {%4,%5,%6,%7}, {%8,%9}, {%0,%1,%2,%3};"
        : "+f"(d[0]), "+f"(d[1]), "+f"(d[2]), "+f"(d[3])
        : "r"(a[0]), "r"(a[1]), "r"(a[2]), "r"(a[3]), "r"(b[0]), "r"(b[1]));
}

// ================= stream B: CSR build =================

__global__ void zero_kernel() {
    int i = blockIdx.x * blockDim.x + threadIdx.x;
    if (i < N_NODES) g_counts[i] = 0;
    if (i < C_OUT)   { g_sum[i] = 0.f; g_sumsq[i] = 0.f; }
}

__global__ void hist_kernel(const int* __restrict__ E) {
    int i = blockIdx.x * blockDim.x + threadIdx.x;
    if (i >= ET / 4) return;
    int base = i * 4;
    int4 d4;
    if (base < E_RAW) {
        d4 = *(const int4*)(E + E_RAW + base);     // 16B-aligned (E_RAW%4==0)
    } else {
        int b = base - E_RAW;
        d4 = make_int4(b, b + 1, b + 2, b + 3);    // self-loop dst
    }
    int4 r4;
    r4.x = atomicAdd(&g_counts[d4.x], 1);
    r4.y = atomicAdd(&g_counts[d4.y], 1);
    r4.z = atomicAdd(&g_counts[d4.z], 1);
    r4.w = atomicAdd(&g_counts[d4.w], 1);
    *(int4*)(g_rank + base) = r4;
}

__global__ void scan1_kernel() {
    __shared__ int sh[1024];
    int b = blockIdx.x, t = threadIdx.x;
    int i = b * 1024 + t;
    int v = (i < N_NODES) ? g_counts[i] : 0;
    sh[t] = v;
    __syncthreads();
    for (int off = 1; off < 1024; off <<= 1) {
        int add = (t >= off) ? sh[t - off] : 0;
        __syncthreads();
        sh[t] += add;
        __syncthreads();
    }
    if (i < N_NODES) g_offsets[i + 1] = sh[t];
    if (t == 1023) g_bsum[b] = sh[1023];
}

__global__ void scan2_kernel() {
    __shared__ int sh[64];
    int t = threadIdx.x;
    int v = (t < NB_SCAN) ? g_bsum[t] : 0;
    sh[t] = v;
    __syncthreads();
    for (int off = 1; off < 64; off <<= 1) {
        int add = (t >= off) ? sh[t - off] : 0;
        __syncthreads();
        sh[t] += add;
        __syncthreads();
    }
    if (t < NB_SCAN) g_boff[t] = sh[t] - v;
    if (t == 0) g_offsets[0] = 0;
}

__global__ void scatter_kernel(const int* __restrict__ E) {
    int g = blockIdx.x * blockDim.x + threadIdx.x;
    if (g >= ET / 4) return;
    int base = g * 4;
    int4 s4, d4;
    if (base < E_RAW) {
        s4 = *(const int4*)(E + base);
        d4 = *(const int4*)(E + E_RAW + base);
    } else {
        int b = base - E_RAW;
        s4 = d4 = make_int4(b, b + 1, b + 2, b + 3);
    }
    int4 r4 = *(const int4*)(g_rank + base);
    g_src_sorted[final_off(d4.x) + r4.x] = s4.x;
    g_src_sorted[final_off(d4.y) + r4.y] = s4.y;
    g_src_sorted[final_off(d4.z) + r4.z] = s4.z;
    g_src_sorted[final_off(d4.w) + r4.w] = s4.w;
}

// ================= stream A: transforms =================

__global__ void convb_kernel(const float* __restrict__ Wl, const float* __restrict__ Wr) {
    int i = blockIdx.x * blockDim.x + threadIdx.x;   // over 512*256 = 131072
    if (i >= 512 * IN_F) return;
    int n = i >> 8, k = i & 255;
    const float* W = (n < 256) ? Wl : Wr;
    g_Bh[n * IN_F + k] = __float2half_rn(W[k * 256 + (n & 255)]);
}

__global__ void convx_kernel(const float* __restrict__ X) {
    int i = blockIdx.x * blockDim.x + threadIdx.x;
    const int real = N_NODES * IN_F / 4;
    const int total = N_PAD * IN_F / 4;
    if (i >= total) return;
    __half h[4];
    if (i < real) {
        float4 v = ((const float4*)X)[i];
        h[0] = __float2half_rn(v.x); h[1] = __float2half_rn(v.y);
        h[2] = __float2half_rn(v.z); h[3] = __float2half_rn(v.w);
    } else {
        h[0] = h[1] = h[2] = h[3] = __float2half_rn(0.f);
    }
    ((uint2*)g_Xh)[i] = *(uint2*)h;
}

// ---------------- mma.sync GEMM: Y[50000,512] = X @ [Wl|Wr] ----------------
#define LDB   40               // padded k-stride (halfs) -> conflict-free LDS
#define TSZ   (128 * LDB)      // one operand tile, elems (5120)
#define BUFSZ (2 * TSZ)        // Ah | Bh
#define GSMEM (2 * BUFSZ * 2)  // bytes: 40960

__global__ void __launch_bounds__(256) gemm_mma_kernel() {
    extern __shared__ __align__(16) char dsm[];
    __half* sm = (__half*)dsm;
    uint32_t sb = smem_u32(dsm);

    const int tid = threadIdx.x;
    const int wid = tid >> 5, lane = tid & 31;
    const int wm = wid & 3, wn = wid >> 2;          // 4 warps on M, 2 on N
    const int q = lane >> 2, c2 = (lane & 3) * 2;
    const int bx = blockIdx.x, by = blockIdx.y;
    const int rowG = by * 128;

    float acc[2][8][4];
#pragma unroll
    for (int mt = 0; mt < 2; mt++)
#pragma unroll
        for (int nt = 0; nt < 8; nt++)
#pragma unroll
            for (int j = 0; j < 4; j++) acc[mt][nt][j] = 0.f;

    auto prefetch = [&](int c, int b) {
        const int k0 = c * 32;
        const uint32_t base = sb + b * (BUFSZ * 2);
#pragma unroll
        for (int i = 0; i < 2; i++) {
            int idx = tid + i * 256;
            int r = idx >> 2, seg = idx & 3;
            uint32_t off = (r * LDB + seg * 8) * 2;
            long ga = (long)(rowG + r) * IN_F + k0 + seg * 8;
            long gb = (long)(bx * 128 + r) * IN_F + k0 + seg * 8;
            cp16(base + off,           g_Xh + ga);
            cp16(base + TSZ * 2 + off, g_Bh + gb);
        }
        CP_COMMIT();
    };

    prefetch(0, 0);
    for (int c = 0; c < 8; c++) {
        if (c < 7) { prefetch(c + 1, (c + 1) & 1); CP_WAIT1(); }
        else       { CP_WAIT0(); }
        __syncthreads();

        const __half* Ah = sm + (c & 1) * BUFSZ;
        const __half* Bh = Ah + TSZ;

#pragma unroll
        for (int ks = 0; ks < 2; ks++) {
            const int kk = ks * 16;
            uint32_t ah[2][4];
#pragma unroll
            for (int mt = 0; mt < 2; mt++) {
                int rb = wm * 32 + mt * 16;
                ah[mt][0] = *(const uint32_t*)(Ah + (rb + q) * LDB + kk + c2);
                ah[mt][1] = *(const uint32_t*)(Ah + (rb + q + 8) * LDB + kk + c2);
                ah[mt][2] = *(const uint32_t*)(Ah + (rb + q) * LDB + kk + c2 + 8);
                ah[mt][3] = *(const uint32_t*)(Ah + (rb + q + 8) * LDB + kk + c2 + 8);
            }
            uint32_t bh[8][2];
#pragma unroll
            for (int nt = 0; nt < 8; nt++) {
                int nb = wn * 64 + nt * 8;
                bh[nt][0] = *(const uint32_t*)(Bh + (nb + q) * LDB + kk + c2);
                bh[nt][1] = *(const uint32_t*)(Bh + (nb + q) * LDB + kk + c2 + 8);
            }
#pragma unroll
            for (int mt = 0; mt < 2; mt++)
#pragma unroll
                for (int nt = 0; nt < 8; nt++)
                    mma_fp16(acc[mt][nt], ah[mt], bh[nt]);
        }
        __syncthreads();
    }

    const int colBase = (bx & 1) * 128;
    if (bx < 2) {   // xl -> fp16
#pragma unroll
        for (int mt = 0; mt < 2; mt++) {
            int r0 = rowG + wm * 32 + mt * 16 + q;
#pragma unroll
            for (int nt = 0; nt < 8; nt++) {
                int col = colBase + wn * 64 + nt * 8 + c2;
                if (r0 < N_NODES)
                    *(__half2*)(g_xlh + (long)r0 * HC + col) =
                        __floats2half2_rn(acc[mt][nt][0], acc[mt][nt][1]);
                if (r0 + 8 < N_NODES)
                    *(__half2*)(g_xlh + (long)(r0 + 8) * HC + col) =
                        __floats2half2_rn(acc[mt][nt][2], acc[mt][nt][3]);
            }
        }
    } else {        // xr -> fp32
#pragma unroll
        for (int mt = 0; mt < 2; mt++) {
            int r0 = rowG + wm * 32 + mt * 16 + q;
#pragma unroll
            for (int nt = 0; nt < 8; nt++) {
                int col = colBase + wn * 64 + nt * 8 + c2;
                if (r0 < N_NODES)
                    *(float2*)(g_xr + (long)r0 * HC + col) = make_float2(acc[mt][nt][0], acc[mt][nt][1]);
                if (r0 + 8 < N_NODES)
                    *(float2*)(g_xr + (long)(r0 + 8) * HC + col) = make_float2(acc[mt][nt][2], acc[mt][nt][3]);
            }
        }
    }
}

// ---------------- attention: one warp per destination node ----------------
__device__ __forceinline__ void unpack8(const uint4& u, float* f) {
    float2 a = __half22float2(*(const __half2*)&u.x);
    float2 b = __half22float2(*(const __half2*)&u.y);
    float2 c = __half22float2(*(const __half2*)&u.z);
    float2 d = __half22float2(*(const __half2*)&u.w);
    f[0] = a.x; f[1] = a.y; f[2] = b.x; f[3] = b.y;
    f[4] = c.x; f[5] = c.y; f[6] = d.x; f[7] = d.y;
}

__global__ void attn_kernel(const float* __restrict__ att,
                            const float* __restrict__ bias) {
    __shared__ float bsum[C_OUT];
    __shared__ float bsq[C_OUT];
    int tid = threadIdx.x;
    if (tid < C_OUT) { bsum[tid] = 0.f; bsq[tid] = 0.f; }
    __syncthreads();

    int warp = (blockIdx.x * blockDim.x + tid) >> 5;
    int lane = tid & 31;

    if (warp < N_NODES) {
        int dst = warp;
        const float4* xr4 = ((const float4*)g_xr) + (long)dst * 64 + lane * 2;
        float4 r0 = xr4[0], r1 = xr4[1];
        float xrv[8] = {r0.x, r0.y, r0.z, r0.w, r1.x, r1.y, r1.z, r1.w};
        float4 a0 = ((const float4*)att)[lane * 2];
        float4 a1 = ((const float4*)att)[lane * 2 + 1];
        float attv[8] = {a0.x, a0.y, a0.z, a0.w, a1.x, a1.y, a1.z, a1.w};

        float m = -1e30f, denom = 0.f;
        float acc[8] = {0.f, 0.f, 0.f, 0.f, 0.f, 0.f, 0.f, 0.f};

        const int e0 = final_off(dst), e1 = final_off(dst + 1);
        int e = e0;
        const int nq = (e1 - e0) >> 2;

        for (int itq = 0; itq < nq; itq++, e += 4) {
            uint4 U[4];
#pragma unroll
            for (int u = 0; u < 4; u++) {
                int s = g_src_sorted[e + u];
                U[u] = *(((const uint4*)(g_xlh + (long)s * HC)) + lane);
            }
            float xl4v[4][8];
            float p[4];
#pragma unroll
            for (int u = 0; u < 4; u++) {
                unpack8(U[u], xl4v[u]);
                float pp = 0.f;
#pragma unroll
                for (int j = 0; j < 8; j++) {
                    float t = xl4v[u][j] + xrv[j];
                    t = (t > 0.f) ? t : NEG_SLOPE * t;
                    pp = fmaf(attv[j], t, pp);
                }
                p[u] = pp;
            }
#pragma unroll
            for (int u = 0; u < 4; u++) p[u] += __shfl_xor_sync(0xffffffffu, p[u], 4);
#pragma unroll
            for (int u = 0; u < 4; u++) p[u] += __shfl_xor_sync(0xffffffffu, p[u], 2);
#pragma unroll
            for (int u = 0; u < 4; u++) p[u] += __shfl_xor_sync(0xffffffffu, p[u], 1);

            // group-max online softmax: one rescale + 5 exps per 4 edges (exact)
            float gm = fmaxf(fmaxf(p[0], p[1]), fmaxf(p[2], p[3]));
            float mn = fmaxf(m, gm);
            float sc = __expf(m - mn);
            float w0 = __expf(p[0] - mn);
            float w1 = __expf(p[1] - mn);
            float w2 = __expf(p[2] - mn);
            float w3 = __expf(p[3] - mn);
            m = mn;
            denom = fmaf(denom, sc, (w0 + w1) + (w2 + w3));
#pragma unroll
            for (int j = 0; j < 8; j++) {
                float t = w0 * xl4v[0][j];
                t = fmaf(w1, xl4v[1][j], t);
                t = fmaf(w2, xl4v[2][j], t);
                t = fmaf(w3, xl4v[3][j], t);
                acc[j] = fmaf(acc[j], sc, t);
            }
        }
        for (; e < e1; e++) {
            int s = g_src_sorted[e];
            uint4 U = *(((const uint4*)(g_xlh + (long)s * HC)) + lane);
            float xlv[8];
            unpack8(U, xlv);
            float pp = 0.f;
#pragma unroll
            for (int j = 0; j < 8; j++) {
                float t = xlv[j] + xrv[j];
                t = (t > 0.f) ? t : NEG_SLOPE * t;
                pp = fmaf(attv[j], t, pp);
            }
            pp += __shfl_xor_sync(0xffffffffu, pp, 4);
            pp += __shfl_xor_sync(0xffffffffu, pp, 2);
            pp += __shfl_xor_sync(0xffffffffu, pp, 1);
            float mn = fmaxf(m, pp);
            float sc = __expf(m - mn);
            float w  = __expf(pp - mn);
            m = mn;
            denom = fmaf(denom, sc, w);
#pragma unroll
            for (int j = 0; j < 8; j++) acc[j] = fmaf(acc[j], sc, w * xlv[j]);
        }

        float inv = 1.f / (denom + 1e-16f);
        float v[8];
#pragma unroll
        for (int j = 0; j < 8; j++) v[j] = acc[j] * inv;
#pragma unroll
        for (int j = 0; j < 8; j++) {
            v[j] += __shfl_xor_sync(0xffffffffu, v[j], 8);
            v[j] += __shfl_xor_sync(0xffffffffu, v[j], 16);
        }
        if (lane < 8) {
#pragma unroll
            for (int j = 0; j < 8; j++) {
                int c = lane * 8 + j;
                float o = 0.25f * v[j] + bias[c];
                g_out[(long)dst * C_OUT + c] = o;
                atomicAdd(&bsum[c], o);
                atomicAdd(&bsq[c], o * o);
            }
        }
    }
    __syncthreads();
    if (tid < C_OUT) {
        atomicAdd(&g_sum[tid], bsum[tid]);
        atomicAdd(&g_sumsq[tid], bsq[tid]);
    }
}

// ---------------- GraphNorm ----------------
__global__ void finalize_kernel(const float* __restrict__ gw,
                                const float* __restrict__ gms) {
    int c = threadIdx.x;
    const float invN = 1.f / (float)N_NODES;
    float mu  = g_sum[c] * invN;
    float msq = g_sumsq[c] * invN;
    float a   = gms[c];
    float var = msq - 2.f * a * mu * mu + a * a * mu * mu;
    g_scale[c] = gw[c] * rsqrtf(var + 1e-5f);
    g_shift[c] = a * mu;
}

__global__ void norm_kernel(const float* __restrict__ gb,
                            float* __restrict__ out) {
    int i = blockIdx.x * blockDim.x + threadIdx.x;
    const int total = N_NODES * C_OUT / 4;
    if (i >= total) return;
    float4 v = ((const float4*)g_out)[i];
    int c = (i & 15) * 4;
    v.x = g_scale[c + 0] * (v.x - g_shift[c + 0]) + gb[c + 0];
    v.y = g_scale[c + 1] * (v.y - g_shift[c + 1]) + gb[c + 1];
    v.z = g_scale[c + 2] * (v.z - g_shift[c + 2]) + gb[c + 2];
    v.w = g_scale[c + 3] * (v.w - g_shift[c + 3]) + gb[c + 3];
    ((float4*)out)[i] = v;
}

// ---------------- launch (fork-join two-stream capture) ----------------
extern "C" void kernel_launch(void* const* d_in, const int* in_sizes, int n_in,
                              void* d_out, int out_size) {
    const float* X    = (const float*)d_in[0];
    const int*   E    = (const int*)  d_in[1];
    const float* Wl   = (const float*)d_in[2];
    const float* Wr   = (const float*)d_in[3];
    const float* att  = (const float*)d_in[4];
    const float* bias = (const float*)d_in[5];
    const float* gw   = (const float*)d_in[6];
    const float* gb   = (const float*)d_in[7];
    const float* gms  = (const float*)d_in[8];
    float* out = (float*)d_out;

    cudaFuncSetAttribute(gemm_mma_kernel, cudaFuncAttributeMaxDynamicSharedMemorySize, GSMEM);

    // per-call stream/event (kernel_launch runs only a few times pre-capture;
    // graph replay never re-enters this function). Not destroyed: destroying
    // during capture would invalidate the captured graph nodes.
    cudaStream_t sB;
    cudaEvent_t evFork, evJoin;
    cudaStreamCreateWithFlags(&sB, cudaStreamNonBlocking);
    cudaEventCreateWithFlags(&evFork, cudaEventDisableTiming);
    cudaEventCreateWithFlags(&evJoin, cudaEventDisableTiming);

    // fork: stream B inherits capture from the main stream
    cudaEventRecord(evFork, 0);
    cudaStreamWaitEvent(sB, evFork, 0);

    // stream B: CSR build
    zero_kernel<<<(N_NODES + 255) / 256, 256, 0, sB>>>();
    hist_kernel<<<(ET / 4 + 255) / 256, 256, 0, sB>>>(E);
    scan1_kernel<<<NB_SCAN, 1024, 0, sB>>>();
    scan2_kernel<<<1, 64, 0, sB>>>();
    scatter_kernel<<<(ET / 4 + 255) / 256, 256, 0, sB>>>(E);
    cudaEventRecord(evJoin, sB);

    // stream A (main): transforms + GEMM
    convb_kernel<<<(512 * IN_F + 255) / 256, 256>>>(Wl, Wr);
    convx_kernel<<<(N_PAD * IN_F / 4 + 255) / 256, 256>>>(X);
    gemm_mma_kernel<<<dim3(4, N_PAD / 128), 256, GSMEM>>>();

    // join, then attention + norm
    cudaStreamWaitEvent(0, evJoin, 0);
    attn_kernel<<<(N_NODES + 7) / 8, 256>>>(att, bias);
    finalize_kernel<<<1, C_OUT>>>(gw, gms);
    norm_kernel<<<(N_NODES * C_OUT / 4 + 255) / 256, 256>>>(gb, out);
}

// round 17
// speedup vs baseline: 1.4428x; 1.1361x over previous
#include <cuda_runtime.h>
#include <cuda_fp16.h>
#include <cstdint>
#include <math.h>

#define N_NODES 50000
#define N_PAD   50048          // padded to multiple of 128 for GEMM tiles
#define E_RAW   800000
#define ET      (E_RAW + N_NODES)   // 850000 (divisible by 4)
#define IN_F    256
#define HC      256            // HEADS * OUT_F
#define C_OUT   64
#define NEG_SLOPE 0.2f
#define NB_SCAN 49             // ceil(50000/1024)

// ---- scratch (static __device__ arrays; no runtime allocation) ----
__device__ __align__(16) __half g_xlh[N_NODES * HC];   // xl in fp16
__device__ __align__(16) __half g_xrh[N_NODES * HC];   // xr in fp16
__device__ float g_out[N_NODES * C_OUT];
__device__ int   g_counts[N_NODES];
__device__ __align__(16) int g_rank[ET];
__device__ int   g_offsets[N_NODES + 1];   // local (per-1024-block) inclusive scans
__device__ int   g_src_sorted[ET];
__device__ int   g_bsum[64];
__device__ int   g_boff[64];
__device__ float g_sum[C_OUT];
__device__ float g_sumsq[C_OUT];
// fp16 operands
__device__ __align__(16) __half g_Xh[N_PAD * IN_F];
__device__ __align__(16) __half g_Bh[512 * IN_F];   // [n][k]; n<256: Wl col, else Wr

// final exclusive CSR offset of node j
__device__ __forceinline__ int final_off(int j) {
    return (j == 0) ? 0 : (g_offsets[j] + g_boff[(j - 1) >> 10]);
}

// ---------------- helpers ----------------
__device__ __forceinline__ uint32_t smem_u32(const void* p) {
    uint32_t a;
    asm("{ .reg .u64 t; cvta.to.shared.u64 t, %1; cvt.u32.u64 %0, t; }" : "=r"(a) : "l"(p));
    return a;
}
__device__ __forceinline__ void cp16(uint32_t s, const void* g) {
    asm volatile("cp.async.cg.shared.global [%0], [%1], 16;" :: "r"(s), "l"(g));
}
#define CP_COMMIT() asm volatile("cp.async.commit_group;" ::: "memory")
#define CP_WAIT1()  asm volatile("cp.async.wait_group 1;" ::: "memory")
#define CP_WAIT0()  asm volatile("cp.async.wait_group 0;" ::: "memory")

__device__ __forceinline__ void mma_fp16(float* d, const uint32_t* a, const uint32_t* b) {
    asm volatile(
        "mma.sync.aligned.m16n8k16.row.col.f32.f16.f16.f32 "
        "{%0,%1,%2,%3}, {%4,%5,%6,%7}, {%8,%9}, {%0,%1,%2,%3};"
        : "+f"(d[0]), "+f"(d[1]), "+f"(d[2]), "+f"(d[3])
        : "r"(a[0]), "r"(a[1]), "r"(a[2]), "r"(a[3]), "r"(b[0]), "r"(b[1]));
}

// ================= stream B: CSR build =================

__global__ void zero_kernel() {
    int i = blockIdx.x * blockDim.x + threadIdx.x;
    if (i < N_NODES) g_counts[i] = 0;
    if (i < C_OUT)   { g_sum[i] = 0.f; g_sumsq[i] = 0.f; }
}

__global__ void hist_kernel(const int* __restrict__ E) {
    int i = blockIdx.x * blockDim.x + threadIdx.x;
    if (i >= ET / 4) return;
    int base = i * 4;
    int4 d4;
    if (base < E_RAW) {
        d4 = *(const int4*)(E + E_RAW + base);     // 16B-aligned (E_RAW%4==0)
    } else {
        int b = base - E_RAW;
        d4 = make_int4(b, b + 1, b + 2, b + 3);    // self-loop dst
    }
    int4 r4;
    r4.x = atomicAdd(&g_counts[d4.x], 1);
    r4.y = atomicAdd(&g_counts[d4.y], 1);
    r4.z = atomicAdd(&g_counts[d4.z], 1);
    r4.w = atomicAdd(&g_counts[d4.w], 1);
    *(int4*)(g_rank + base) = r4;
}

__global__ void scan1_kernel() {
    __shared__ int sh[1024];
    int b = blockIdx.x, t = threadIdx.x;
    int i = b * 1024 + t;
    int v = (i < N_NODES) ? g_counts[i] : 0;
    sh[t] = v;
    __syncthreads();
    for (int off = 1; off < 1024; off <<= 1) {
        int add = (t >= off) ? sh[t - off] : 0;
        __syncthreads();
        sh[t] += add;
        __syncthreads();
    }
    if (i < N_NODES) g_offsets[i + 1] = sh[t];
    if (t == 1023) g_bsum[b] = sh[1023];
}

__global__ void scan2_kernel() {
    __shared__ int sh[64];
    int t = threadIdx.x;
    int v = (t < NB_SCAN) ? g_bsum[t] : 0;
    sh[t] = v;
    __syncthreads();
    for (int off = 1; off < 64; off <<= 1) {
        int add = (t >= off) ? sh[t - off] : 0;
        __syncthreads();
        sh[t] += add;
        __syncthreads();
    }
    if (t < NB_SCAN) g_boff[t] = sh[t] - v;
    if (t == 0) g_offsets[0] = 0;
}

__global__ void scatter_kernel(const int* __restrict__ E) {
    int g = blockIdx.x * blockDim.x + threadIdx.x;
    if (g >= ET / 4) return;
    int base = g * 4;
    int4 s4, d4;
    if (base < E_RAW) {
        s4 = *(const int4*)(E + base);
        d4 = *(const int4*)(E + E_RAW + base);
    } else {
        int b = base - E_RAW;
        s4 = d4 = make_int4(b, b + 1, b + 2, b + 3);
    }
    int4 r4 = *(const int4*)(g_rank + base);
    g_src_sorted[final_off(d4.x) + r4.x] = s4.x;
    g_src_sorted[final_off(d4.y) + r4.y] = s4.y;
    g_src_sorted[final_off(d4.z) + r4.z] = s4.z;
    g_src_sorted[final_off(d4.w) + r4.w] = s4.w;
}

// ================= stream A: transforms =================

__global__ void convb_kernel(const float* __restrict__ Wl, const float* __restrict__ Wr) {
    int i = blockIdx.x * blockDim.x + threadIdx.x;   // over 512*256 = 131072
    if (i >= 512 * IN_F) return;
    int n = i >> 8, k = i & 255;
    const float* W = (n < 256) ? Wl : Wr;
    g_Bh[n * IN_F + k] = __float2half_rn(W[k * 256 + (n & 255)]);
}

__global__ void convx_kernel(const float* __restrict__ X) {
    int i = blockIdx.x * blockDim.x + threadIdx.x;
    const int real = N_NODES * IN_F / 4;
    const int total = N_PAD * IN_F / 4;
    if (i >= total) return;
    __half h[4];
    if (i < real) {
        float4 v = ((const float4*)X)[i];
        h[0] = __float2half_rn(v.x); h[1] = __float2half_rn(v.y);
        h[2] = __float2half_rn(v.z); h[3] = __float2half_rn(v.w);
    } else {
        h[0] = h[1] = h[2] = h[3] = __float2half_rn(0.f);
    }
    ((uint2*)g_Xh)[i] = *(uint2*)h;
}

// ---------------- mma.sync GEMM: Y[50000,512] = X @ [Wl|Wr] ----------------
// grid(4, 391). KC=64 chunks, depth-2 cp.async, conflict-free scalar LDS.
#define KC    64
#define LDB   72               // padded k-stride (halfs): word-stride 36 -> banks 4q+r, conflict-free
#define TSZ   (128 * LDB)      // one operand tile, elems (9216)
#define BUFSZ (2 * TSZ)        // Ah | Bh
#define GSMEM (2 * BUFSZ * 2)  // bytes: 73728

__global__ void __launch_bounds__(256) gemm_mma_kernel() {
    extern __shared__ __align__(16) char dsm[];
    __half* sm = (__half*)dsm;
    uint32_t sb = smem_u32(dsm);

    const int tid = threadIdx.x;
    const int wid = tid >> 5, lane = tid & 31;
    const int wm = wid & 3, wn = wid >> 2;          // 4 warps on M, 2 on N
    const int q = lane >> 2, c2 = (lane & 3) * 2;
    const int bx = blockIdx.x, by = blockIdx.y;
    const int rowG = by * 128;

    float acc[2][8][4];
#pragma unroll
    for (int mt = 0; mt < 2; mt++)
#pragma unroll
        for (int nt = 0; nt < 8; nt++)
#pragma unroll
            for (int j = 0; j < 4; j++) acc[mt][nt][j] = 0.f;

    auto prefetch = [&](int c, int b) {
        const int k0 = c * KC;
        const uint32_t base = sb + b * (BUFSZ * 2);
#pragma unroll
        for (int i = 0; i < 4; i++) {               // 1024 vecs each for A and B
            int idx = tid + i * 256;
            int r = idx >> 3, seg = idx & 7;
            uint32_t off = (r * LDB + seg * 8) * 2;
            long ga = (long)(rowG + r) * IN_F + k0 + seg * 8;
            long gb = (long)(bx * 128 + r) * IN_F + k0 + seg * 8;
            cp16(base + off,           g_Xh + ga);
            cp16(base + TSZ * 2 + off, g_Bh + gb);
        }
        CP_COMMIT();
    };

    prefetch(0, 0);
    for (int c = 0; c < 4; c++) {
        if (c < 3) { prefetch(c + 1, (c + 1) & 1); CP_WAIT1(); }
        else       { CP_WAIT0(); }
        __syncthreads();

        const __half* Ah = sm + (c & 1) * BUFSZ;
        const __half* Bh = Ah + TSZ;

#pragma unroll
        for (int ks = 0; ks < 4; ks++) {
            const int kk = ks * 16;
            uint32_t ah[2][4];
#pragma unroll
            for (int mt = 0; mt < 2; mt++) {
                int rb = wm * 32 + mt * 16;
                ah[mt][0] = *(const uint32_t*)(Ah + (rb + q) * LDB + kk + c2);
                ah[mt][1] = *(const uint32_t*)(Ah + (rb + q + 8) * LDB + kk + c2);
                ah[mt][2] = *(const uint32_t*)(Ah + (rb + q) * LDB + kk + c2 + 8);
                ah[mt][3] = *(const uint32_t*)(Ah + (rb + q + 8) * LDB + kk + c2 + 8);
            }
            uint32_t bh[8][2];
#pragma unroll
            for (int nt = 0; nt < 8; nt++) {
                int nb = wn * 64 + nt * 8;
                bh[nt][0] = *(const uint32_t*)(Bh + (nb + q) * LDB + kk + c2);
                bh[nt][1] = *(const uint32_t*)(Bh + (nb + q) * LDB + kk + c2 + 8);
            }
#pragma unroll
            for (int mt = 0; mt < 2; mt++)
#pragma unroll
                for (int nt = 0; nt < 8; nt++)
                    mma_fp16(acc[mt][nt], ah[mt], bh[nt]);
        }
        __syncthreads();
    }

    __half* Y = (bx < 2) ? g_xlh : g_xrh;
    const int colBase = (bx & 1) * 128;
#pragma unroll
    for (int mt = 0; mt < 2; mt++) {
        int r0 = rowG + wm * 32 + mt * 16 + q;
#pragma unroll
        for (int nt = 0; nt < 8; nt++) {
            int col = colBase + wn * 64 + nt * 8 + c2;
            if (r0 < N_NODES)
                *(__half2*)(Y + (long)r0 * HC + col) =
                    __floats2half2_rn(acc[mt][nt][0], acc[mt][nt][1]);
            if (r0 + 8 < N_NODES)
                *(__half2*)(Y + (long)(r0 + 8) * HC + col) =
                    __floats2half2_rn(acc[mt][nt][2], acc[mt][nt][3]);
        }
    }
}

// ---------------- attention: one warp per destination node ----------------
// fp16 gathers; half2 LeakyReLU; fp32 dot/softmax/accum.
__device__ __forceinline__ void unpack8(const uint4& u, float* f) {
    float2 a = __half22float2(*(const __half2*)&u.x);
    float2 b = __half22float2(*(const __half2*)&u.y);
    float2 c = __half22float2(*(const __half2*)&u.z);
    float2 d = __half22float2(*(const __half2*)&u.w);
    f[0] = a.x; f[1] = a.y; f[2] = b.x; f[3] = b.y;
    f[4] = c.x; f[5] = c.y; f[6] = d.x; f[7] = d.y;
}

// half2 logit partial: sum_j att[j] * leaky(xl[j]+xr[j]) over this lane's 8 channels
__device__ __forceinline__ float logit8(const uint4& U, const __half2* xr2, const float* attv) {
    const __half2 h2z = __float2half2_rn(0.f);
    const __half2 c02 = __float2half2_rn(NEG_SLOPE);
    const __half2* xl2 = (const __half2*)&U;
    float pp = 0.f;
#pragma unroll
    for (int k = 0; k < 4; k++) {
        __half2 t2 = __hadd2(xl2[k], xr2[k]);
        __half2 l2 = __hfma2(__hmin2(t2, h2z), c02, __hmax2(t2, h2z));
        float2 lf = __half22float2(l2);
        pp = fmaf(attv[2 * k], lf.x, pp);
        pp = fmaf(attv[2 * k + 1], lf.y, pp);
    }
    return pp;
}

__global__ void attn_kernel(const float* __restrict__ att,
                            const float* __restrict__ bias) {
    __shared__ float bsum[C_OUT];
    __shared__ float bsq[C_OUT];
    int tid = threadIdx.x;
    if (tid < C_OUT) { bsum[tid] = 0.f; bsq[tid] = 0.f; }
    __syncthreads();

    int warp = (blockIdx.x * blockDim.x + tid) >> 5;
    int lane = tid & 31;

    if (warp < N_NODES) {
        int dst = warp;
        uint4 Uxr = *(((const uint4*)(g_xrh + (long)dst * HC)) + lane);
        __half2 xr2[4];
        xr2[0] = *(const __half2*)&Uxr.x; xr2[1] = *(const __half2*)&Uxr.y;
        xr2[2] = *(const __half2*)&Uxr.z; xr2[3] = *(const __half2*)&Uxr.w;
        float4 a0 = ((const float4*)att)[lane * 2];
        float4 a1 = ((const float4*)att)[lane * 2 + 1];
        float attv[8] = {a0.x, a0.y, a0.z, a0.w, a1.x, a1.y, a1.z, a1.w};

        float m = -1e30f, denom = 0.f;
        float acc[8] = {0.f, 0.f, 0.f, 0.f, 0.f, 0.f, 0.f, 0.f};

        const int e0 = final_off(dst), e1 = final_off(dst + 1);
        int e = e0;
        const int nq = (e1 - e0) >> 2;

        for (int itq = 0; itq < nq; itq++, e += 4) {
            uint4 U[4];
#pragma unroll
            for (int u = 0; u < 4; u++) {
                int s = g_src_sorted[e + u];
                U[u] = *(((const uint4*)(g_xlh + (long)s * HC)) + lane);
            }
            float p[4];
#pragma unroll
            for (int u = 0; u < 4; u++) p[u] = logit8(U[u], xr2, attv);
#pragma unroll
            for (int u = 0; u < 4; u++) p[u] += __shfl_xor_sync(0xffffffffu, p[u], 4);
#pragma unroll
            for (int u = 0; u < 4; u++) p[u] += __shfl_xor_sync(0xffffffffu, p[u], 2);
#pragma unroll
            for (int u = 0; u < 4; u++) p[u] += __shfl_xor_sync(0xffffffffu, p[u], 1);

            // group-max online softmax: one rescale + 5 exps per 4 edges (exact)
            float gm = fmaxf(fmaxf(p[0], p[1]), fmaxf(p[2], p[3]));
            float mn = fmaxf(m, gm);
            float sc = __expf(m - mn);
            float w0 = __expf(p[0] - mn);
            float w1 = __expf(p[1] - mn);
            float w2 = __expf(p[2] - mn);
            float w3 = __expf(p[3] - mn);
            m = mn;
            denom = fmaf(denom, sc, (w0 + w1) + (w2 + w3));
            float x0[8], x1[8], x2[8], x3[8];
            unpack8(U[0], x0); unpack8(U[1], x1); unpack8(U[2], x2); unpack8(U[3], x3);
#pragma unroll
            for (int j = 0; j < 8; j++) {
                float t = w0 * x0[j];
                t = fmaf(w1, x1[j], t);
                t = fmaf(w2, x2[j], t);
                t = fmaf(w3, x3[j], t);
                acc[j] = fmaf(acc[j], sc, t);
            }
        }
        for (; e < e1; e++) {
            int s = g_src_sorted[e];
            uint4 U = *(((const uint4*)(g_xlh + (long)s * HC)) + lane);
            float pp = logit8(U, xr2, attv);
            pp += __shfl_xor_sync(0xffffffffu, pp, 4);
            pp += __shfl_xor_sync(0xffffffffu, pp, 2);
            pp += __shfl_xor_sync(0xffffffffu, pp, 1);
            float mn = fmaxf(m, pp);
            float sc = __expf(m - mn);
            float w  = __expf(pp - mn);
            m = mn;
            denom = fmaf(denom, sc, w);
            float xlv[8];
            unpack8(U, xlv);
#pragma unroll
            for (int j = 0; j < 8; j++) acc[j] = fmaf(acc[j], sc, w * xlv[j]);
        }

        float inv = 1.f / (denom + 1e-16f);
        float v[8];
#pragma unroll
        for (int j = 0; j < 8; j++) v[j] = acc[j] * inv;
#pragma unroll
        for (int j = 0; j < 8; j++) {
            v[j] += __shfl_xor_sync(0xffffffffu, v[j], 8);
            v[j] += __shfl_xor_sync(0xffffffffu, v[j], 16);
        }
        if (lane < 8) {
#pragma unroll
            for (int j = 0; j < 8; j++) {
                int c = lane * 8 + j;
                float o = 0.25f * v[j] + bias[c];
                g_out[(long)dst * C_OUT + c] = o;
                atomicAdd(&bsum[c], o);
                atomicAdd(&bsq[c], o * o);
            }
        }
    }
    __syncthreads();
    if (tid < C_OUT) {
        atomicAdd(&g_sum[tid], bsum[tid]);
        atomicAdd(&g_sumsq[tid], bsq[tid]);
    }
}

// ---------------- GraphNorm (finalize fused: each block recomputes scale/shift) ----------------
__global__ void norm_kernel(const float* __restrict__ gw,
                            const float* __restrict__ gb,
                            const float* __restrict__ gms,
                            float* __restrict__ out) {
    __shared__ float s_scale[C_OUT], s_shift[C_OUT];
    int t = threadIdx.x;
    if (t < C_OUT) {
        const float invN = 1.f / (float)N_NODES;
        float mu  = g_sum[t] * invN;
        float msq = g_sumsq[t] * invN;
        float a   = gms[t];
        float var = msq - 2.f * a * mu * mu + a * a * mu * mu;
        s_scale[t] = gw[t] * rsqrtf(var + 1e-5f);
        s_shift[t] = a * mu;
    }
    __syncthreads();
    int i = blockIdx.x * blockDim.x + t;
    const int total = N_NODES * C_OUT / 4;
    if (i >= total) return;
    float4 v = ((const float4*)g_out)[i];
    int c = (i & 15) * 4;
    v.x = s_scale[c + 0] * (v.x - s_shift[c + 0]) + gb[c + 0];
    v.y = s_scale[c + 1] * (v.y - s_shift[c + 1]) + gb[c + 1];
    v.z = s_scale[c + 2] * (v.z - s_shift[c + 2]) + gb[c + 2];
    v.w = s_scale[c + 3] * (v.w - s_shift[c + 3]) + gb[c + 3];
    ((float4*)out)[i] = v;
}

// ---------------- launch (fork-join two-stream capture) ----------------
extern "C" void kernel_launch(void* const* d_in, const int* in_sizes, int n_in,
                              void* d_out, int out_size) {
    const float* X    = (const float*)d_in[0];
    const int*   E    = (const int*)  d_in[1];
    const float* Wl   = (const float*)d_in[2];
    const float* Wr   = (const float*)d_in[3];
    const float* att  = (const float*)d_in[4];
    const float* bias = (const float*)d_in[5];
    const float* gw   = (const float*)d_in[6];
    const float* gb   = (const float*)d_in[7];
    const float* gms  = (const float*)d_in[8];
    float* out = (float*)d_out;

    cudaFuncSetAttribute(gemm_mma_kernel, cudaFuncAttributeMaxDynamicSharedMemorySize, GSMEM);

    cudaStream_t sB;
    cudaEvent_t evFork, evJoin;
    cudaStreamCreateWithFlags(&sB, cudaStreamNonBlocking);
    cudaEventCreateWithFlags(&evFork, cudaEventDisableTiming);
    cudaEventCreateWithFlags(&evJoin, cudaEventDisableTiming);

    cudaEventRecord(evFork, 0);
    cudaStreamWaitEvent(sB, evFork, 0);

    // stream B: CSR build
    zero_kernel<<<(N_NODES + 255) / 256, 256, 0, sB>>>();
    hist_kernel<<<(ET / 4 + 255) / 256, 256, 0, sB>>>(E);
    scan1_kernel<<<NB_SCAN, 1024, 0, sB>>>();
    scan2_kernel<<<1, 64, 0, sB>>>();
    scatter_kernel<<<(ET / 4 + 255) / 256, 256, 0, sB>>>(E);
    cudaEventRecord(evJoin, sB);

    // stream A (main): transforms + GEMM
    convb_kernel<<<(512 * IN_F + 255) / 256, 256>>>(Wl, Wr);
    convx_kernel<<<(N_PAD * IN_F / 4 + 255) / 256, 256>>>(X);
    gemm_mma_kernel<<<dim3(4, N_PAD / 128), 256, GSMEM>>>();

    // join, then attention + norm
    cudaStreamWaitEvent(0, evJoin, 0);
    attn_kernel<<<(N_NODES + 7) / 8, 256>>>(att, bias);
    norm_kernel<<<(N_NODES * C_OUT / 4 + 255) / 256, 256>>>(gw, gb, gms, out);
}